// round 9
// baseline (speedup 1.0000x reference)
#include <cuda_runtime.h>
#include <cuda_fp16.h>
#include <cstdint>

// Problem constants
#define T_    4
#define B_    32
#define C_    512
#define HW_   256
#define NH    8
#define HD    64
#define SLICE 4194304      // B*C*HW = one time slice
#define TOTAL 16777216     // T*B*C*HW
#define CN    131072       // C*HW per (t,b)

// ---------------------------------------------------------------------------
// helpers
// ---------------------------------------------------------------------------
__device__ __forceinline__ uint32_t smem_to_u32(const void* smem_ptr) {
    uint32_t addr;
    asm("{ .reg .u64 tmp; cvta.to.shared.u64 tmp, %1; cvt.u32.u64 %0, tmp; }"
        : "=r"(addr) : "l"(smem_ptr));
    return addr;
}

__device__ __forceinline__ void cp16(uint32_t dst, const void* src) {
    asm volatile("cp.async.cg.shared.global [%0], [%1], 16;" :: "r"(dst), "l"(src));
}

__device__ __forceinline__ void ldsm4(uint32_t* r, uint32_t addr) {
    asm volatile("ldmatrix.sync.aligned.m8n8.x4.shared.b16 {%0,%1,%2,%3}, [%4];"
                 : "=r"(r[0]), "=r"(r[1]), "=r"(r[2]), "=r"(r[3]) : "r"(addr));
}

__device__ __forceinline__ void mma16816h(float* c, const uint32_t* a,
                                          uint32_t b0, uint32_t b1) {
    asm volatile(
        "mma.sync.aligned.m16n8k16.row.col.f32.f16.f16.f32 "
        "{%0,%1,%2,%3}, {%4,%5,%6,%7}, {%8,%9}, {%0,%1,%2,%3};"
        : "+f"(c[0]), "+f"(c[1]), "+f"(c[2]), "+f"(c[3])
        : "r"(a[0]), "r"(a[1]), "r"(a[2]), "r"(a[3]), "r"(b0), "r"(b1));
}

// ---------------------------------------------------------------------------
// Scratch (static device globals)
// ---------------------------------------------------------------------------
__device__ __half g_xsB[TOTAL];              // x spikes, per-b matrix [b][n'=0..1023][c]
                                             //   n' = (n>>3)*32 + t*8 + (n&7)
__device__ __half g_qT[TOTAL];               // q spikes, [tb][n][c] fp16
__device__ __half g_ks[TOTAL];               // k spikes, [t,b,c,n] fp16
__device__ __half g_vs[TOTAL];               // v spikes, [t,b,c,n] fp16
__device__ __half g_x2T[TOTAL];              // x2 spikes, [tb][n][c] fp16
__device__ __half g_attnT[2 * B_ * NH * HD * HD];   // [chunk,b,h][de][dh]
__device__ __half g_wsplit[2u * 2048u * 512u];      // [split: 0=mid',1=hi][2048][512]
__device__ float  g_scale[3 * C_];
__device__ float  g_bias [3 * C_];

// ---------------------------------------------------------------------------
// Prep: exact 2-way fp16 split of the 4 weight matrices
//   w = hi + mid' * 2^-12   (mid' = fp16(r1*4096))
// ---------------------------------------------------------------------------
__global__ void wsplit_kernel(const float* __restrict__ Wq, const float* __restrict__ Wk,
                              const float* __restrict__ Wv, const float* __restrict__ Wp,
                              __half* __restrict__ ws)
{
    int i = blockIdx.x * 256 + threadIdx.x;      // 0 .. 2048*512-1
    int r = i >> 9;
    int kk = i & 511;
    const float* W = (r < 512) ? Wq : (r < 1024) ? Wk : (r < 1536) ? Wv : Wp;
    float w = W[(size_t)(r & 511) * 512 + kk];
    __half hi = __float2half_rn(w);
    float r1 = w - __half2float(hi);
    __half mid = __float2half_rn(r1 * 4096.0f);
    ws[i]            = mid;     // split 0 = scaled mid (accumulated first)
    ws[1048576u + i] = hi;      // split 1 = hi
}

__global__ void sb_kernel(const float* __restrict__ qs, const float* __restrict__ qb,
                          const float* __restrict__ ks, const float* __restrict__ kb,
                          const float* __restrict__ vs, const float* __restrict__ vb,
                          float* __restrict__ gs, float* __restrict__ gb)
{
    int i = blockIdx.x * 256 + threadIdx.x;
    if (i >= 1536) return;
    if (i < 512)       { gs[i] = qs[i];        gb[i] = qb[i]; }
    else if (i < 1024) { gs[i] = ks[i - 512];  gb[i] = kb[i - 512]; }
    else               { gs[i] = vs[i - 1024]; gb[i] = vb[i - 1024]; }
}

// ---------------------------------------------------------------------------
// K1: shortcut LIF on x fused with transpose -> xsB fp16 [b][n'][c]
//   n' = (n>>3)*32 + t*8 + (n&7)   (t folded into the GEMM N dimension)
// ---------------------------------------------------------------------------
__global__ void lif_in_trans_kernel(const float* __restrict__ x,
                                    __half* __restrict__ xsB)
{
    __shared__ __half tile[64][65];
    int nblk = blockIdx.x, cblk = blockIdx.y, b = blockIdx.z;
    int tid = threadIdx.x;

    float v[16];
#pragma unroll
    for (int p = 0; p < 16; p++) v[p] = 0.f;

    __half* D = xsB + (size_t)b * (1024 * 512);

#pragma unroll
    for (int t = 0; t < T_; t++) {
        if (t) __syncthreads();
#pragma unroll
        for (int p = 0; p < 16; p++) {
            int c_l = p * 4 + (tid >> 6), n_l = tid & 63;
            float xv = x[(size_t)t * SLICE +
                         ((size_t)(b * C_ + cblk * 64 + c_l)) * HW_ + nblk * 64 + n_l];
            v[p] = v[p] + (xv - v[p]) * 0.5f;
            float s = (v[p] >= 1.0f) ? 1.0f : 0.0f;
            if (s != 0.f) v[p] = 0.f;
            tile[c_l][n_l] = __float2half(s);
        }
        __syncthreads();
#pragma unroll
        for (int p = 0; p < 16; p++) {
            int c_l = tid & 63, n_l = p * 4 + (tid >> 6);
            int n = nblk * 64 + n_l;
            int nprime = (n >> 3) * 32 + t * 8 + (n & 7);
            D[(size_t)nprime * C_ + cblk * 64 + c_l] = tile[c_l][n_l];
        }
    }
}

// ---------------------------------------------------------------------------
// HMMA GEMM: CTA 128x128, 2x4 warps of 64x32, TWO-stage double buffer (r6 loop)
// MODE 0: qkv. B = xsB per b (1024 rows, t folded: jj index == t). 16 stages
//         (8 mid' + 8 hi, exact). Epilogue: BN -> LIF(vth=1) -> qT/ks/vs/vout.
//         grid (8 nblk, 12 mtile, 32 b)
// MODE 1: proj, hi-split ONLY (8 stages). Epilogue: (acc+cb)*sc+bi+identity.
//         grid (2 ntile, 4 mtile, 128 tb)
// ---------------------------------------------------------------------------
#define STAGE_BYTES 36864
#define A_BYTES     18432
#define SM_STRIDE   136          // halves; 272B row stride

template<int MODE>
__global__ void __launch_bounds__(256, 2) gemm_hmma_kernel(
    const __half* __restrict__ wsplit,            // [2][2048][512]
    const __half* __restrict__ Bmat,              // MODE0: xsB ; MODE1: x2T
    __half* __restrict__ qT, __half* __restrict__ ksp, __half* __restrict__ vsp,
    float* __restrict__ vout,
    const float* __restrict__ scale, const float* __restrict__ bias,
    const float* __restrict__ cbias, const float* __restrict__ identity,
    float* __restrict__ outp, int wrow_base)
{
    constexpr int NS = (MODE == 0) ? 16 : 8;
    extern __shared__ __align__(128) char smem[];
    uint32_t smem_u = smem_to_u32(smem);
    const int tid = threadIdx.x;
    const int wid = tid >> 5, lane = tid & 31;
    const int wm = wid >> 2, wn = wid & 3;         // 2 x 4 warp grid, 64x32 tiles
    const int n0 = blockIdx.x * 128;
    const int m0 = blockIdx.y * 128;
    const int bz = blockIdx.z;
    const char* Bbase = (MODE == 0)
        ? (const char*)(Bmat + (size_t)bz * (1024 * 512))
        : (const char*)(Bmat + (size_t)bz * CN);

    float acc[4][4][4];
#pragma unroll
    for (int i = 0; i < 4; i++)
#pragma unroll
        for (int j = 0; j < 4; j++)
#pragma unroll
            for (int e = 0; e < 4; e++) acc[i][j][e] = 0.f;

    auto cp_stage = [&](int s) {
        int buf = s & 1;
        int split = (MODE == 0) ? (s >> 3) : 1;   // MODE1: hi only
        int kA = (s & 7) << 6;
        const char* Ag = (const char*)wsplit
                       + ((size_t)split * 2048 + (size_t)(wrow_base + m0)) * 1024
                       + (size_t)kA * 2;
        const char* Bg = Bbase + (size_t)n0 * 1024 + (size_t)kA * 2;
        uint32_t sA = smem_u + buf * STAGE_BYTES;
        uint32_t sB = sA + A_BYTES;
#pragma unroll
        for (int p = 0; p < 4; p++) {
            int lin = p * 256 + tid;
            int r = lin >> 3, sg = lin & 7;
            cp16(sA + r * 144 + sg * 16, Ag + (size_t)r * 1024 + sg * 16);
            cp16(sB + r * 144 + sg * 16, Bg + (size_t)r * 1024 + sg * 16);
        }
        asm volatile("cp.async.commit_group;");
    };

    cp_stage(0);

    for (int s = 0; s < NS; s++) {
        if (s + 1 < NS) {
            cp_stage(s + 1);
            asm volatile("cp.async.wait_group 1;");
        } else {
            asm volatile("cp.async.wait_group 0;");
        }
        __syncthreads();

        uint32_t sA = smem_u + (s & 1) * STAGE_BYTES;
        uint32_t sB = sA + A_BYTES;

#pragma unroll
        for (int kk = 0; kk < 4; kk++) {
            uint32_t a[4][4];
#pragma unroll
            for (int i = 0; i < 4; i++) {
                uint32_t row = wm * 64 + i * 16 + (lane & 15);
                uint32_t col = kk * 16 + ((lane >> 4) << 3);
                ldsm4(a[i], sA + (row * 72 + col) * 2);
            }
            uint32_t bf[2][4];
#pragma unroll
            for (int j2 = 0; j2 < 2; j2++) {
                uint32_t row = wn * 32 + j2 * 16 + (lane & 7) + ((lane >> 4) << 3);
                uint32_t col = kk * 16 + (((lane >> 3) & 1) << 3);
                ldsm4(bf[j2], sB + (row * 72 + col) * 2);
            }
#pragma unroll
            for (int i = 0; i < 4; i++)
#pragma unroll
                for (int jj = 0; jj < 4; jj++) {
                    uint32_t b0 = bf[jj >> 1][(jj & 1) * 2 + 0];
                    uint32_t b1 = bf[jj >> 1][(jj & 1) * 2 + 1];
                    mma16816h(acc[i][jj], a[i], b0, b1);
                }
        }
        if (MODE == 0 && s == 7) {
            // fold the scaled mid split: acc *= 2^-12 (exact)
#pragma unroll
            for (int i = 0; i < 4; i++)
#pragma unroll
                for (int j = 0; j < 4; j++)
#pragma unroll
                    for (int e = 0; e < 4; e++) acc[i][j][e] *= 0.000244140625f;
        }
        __syncthreads();
    }

    int g = lane >> 2, tg = lane & 3;

    if (MODE == 0) {
        // ---- BN + LIF (vth=1) in registers: jj == t ----
        __half (*sm)[SM_STRIDE] = (__half(*)[SM_STRIDE])smem;
#pragma unroll
        for (int i = 0; i < 4; i++) {
#pragma unroll
            for (int eh = 0; eh < 2; eh++) {
                int rl = wm * 64 + i * 16 + g + eh * 8;
                float sc = scale[m0 + rl], bi = bias[m0 + rl];
#pragma unroll
                for (int e1 = 0; e1 < 2; e1++) {
                    int nl = wn * 8 + 2 * tg + e1;        // n_local 0..31
                    float v = 0.f;
#pragma unroll
                    for (int t = 0; t < T_; t++) {
                        float xv = acc[i][t][eh * 2 + e1] * sc + bi;
                        v = v + (xv - v) * 0.5f;
                        float ss = (v >= 1.0f) ? 1.0f : 0.0f;
                        if (ss != 0.f) v = 0.f;
                        sm[rl][t * 32 + nl] = __float2half(ss);
                    }
                }
            }
        }
        __syncthreads();

        int tt   = blockIdx.y >> 2;      // 0 q, 1 k, 2 v
        int msub = blockIdx.y & 3;       // 128-row block within tensor
        int b    = bz;
        int nb   = blockIdx.x;           // n base = nb*32

        if (tt == 0) {
            // qT[(t*32+b)*256 + nb*32 + n][msub*128 + half*64 + c]
            int rid = tid >> 1, half = tid & 1;
            int t = rid >> 5, n = rid & 31;
            __half tmp[64];
#pragma unroll
            for (int c = 0; c < 64; c++) tmp[c] = sm[half * 64 + c][t * 32 + n];
            __half* dst = qT + ((size_t)((t * 32 + b) * 256 + nb * 32 + n)) * 512
                             + msub * 128 + half * 64;
#pragma unroll
            for (int u = 0; u < 8; u++) ((uint4*)dst)[u] = ((uint4*)tmp)[u];
        } else {
            __half* base = (tt == 1) ? ksp : vsp;
#pragma unroll
            for (int p = 0; p < 2; p++) {
                int rid = p * 256 + tid;       // 0..511
                int t = rid >> 7, cl = rid & 127;
                const uint4* srow = (const uint4*)&sm[cl][t * 32];
                __half* dst = base + (size_t)t * SLICE
                            + ((size_t)(b * C_ + msub * 128 + cl)) * HW_ + nb * 32;
#pragma unroll
                for (int u = 0; u < 4; u++) ((uint4*)dst)[u] = srow[u];
            }
            if (tt == 2) {
                // vout fp32 [t,b,h,n,hd]
                int t = tid >> 6, rem = tid & 63;
                int hl = rem >> 5, n = rem & 31;
                int h = msub * 2 + hl;
                float* dst = vout + ((((size_t)(t * 32 + b) * NH + h) * HW_) + nb * 32 + n) * HD;
#pragma unroll
                for (int c4 = 0; c4 < 16; c4++) {
                    float4 f;
                    f.x = __half2float(sm[hl * 64 + c4 * 4 + 0][t * 32 + n]);
                    f.y = __half2float(sm[hl * 64 + c4 * 4 + 1][t * 32 + n]);
                    f.z = __half2float(sm[hl * 64 + c4 * 4 + 2][t * 32 + n]);
                    f.w = __half2float(sm[hl * 64 + c4 * 4 + 3][t * 32 + n]);
                    ((float4*)dst)[c4] = f;
                }
            }
        }
    } else {
        // ---- proj epilogue ----
#pragma unroll
        for (int i = 0; i < 4; i++) {
            int mloc = m0 + wm * 64 + i * 16 + g;
#pragma unroll
            for (int half = 0; half < 2; half++) {
                int c = mloc + half * 8;
                float sc = scale[c], bi = bias[c], cb = cbias[c];
                float* dst = outp + (size_t)bz * CN + (size_t)c * HW_;
                const float* idp = identity + (size_t)bz * CN + (size_t)c * HW_;
#pragma unroll
                for (int jj = 0; jj < 4; jj++) {
                    int col = n0 + wn * 32 + jj * 8 + 2 * tg;
                    float2 id2 = *(const float2*)&idp[col];
                    float2 v2;
                    v2.x = (acc[i][jj][half * 2 + 0] + cb) * sc + bi + id2.x;
                    v2.y = (acc[i][jj][half * 2 + 1] + cb) * sc + bi + id2.y;
                    *(float2*)&dst[col] = v2;
                }
            }
        }
    }
}

// ---------------------------------------------------------------------------
// attn HMMA: attnT[chunk,b,h][de][dh] = (1/16) * sum_{t in chunk, s} v[de,s]*k[dh,s]
// ---------------------------------------------------------------------------
__global__ void __launch_bounds__(128) attn_hmma_kernel(
    const __half* __restrict__ ksp, const __half* __restrict__ vsp,
    __half* __restrict__ attnT)
{
    __shared__ __half sv[64][72];
    __shared__ __half sk[64][72];
    uint32_t sv_u = smem_to_u32(&sv[0][0]);
    uint32_t sk_u = smem_to_u32(&sk[0][0]);

    int cbh = blockIdx.x;
    int h = cbh & 7, b = (cbh >> 3) & 31, chunk = cbh >> 8;
    int tid = threadIdx.x;
    int wid = tid >> 5, lane = tid & 31;

    float acc[8][4];
#pragma unroll
    for (int j = 0; j < 8; j++)
#pragma unroll
        for (int e = 0; e < 4; e++) acc[j][e] = 0.f;

    for (int st = 0; st < 8; st++) {
        int t = chunk * 2 + (st >> 2);
        int n0 = (st & 3) * 64;
        size_t base = (size_t)t * SLICE + ((size_t)(b * C_ + h * HD)) * HW_ + n0;
#pragma unroll
        for (int l = 0; l < 4; l++) {
            int lin = l * 128 + tid;
            int r = lin >> 3, sg = lin & 7;
            *(uint4*)((char*)sv + r * 144 + sg * 16) =
                *(const uint4*)(vsp + base + (size_t)r * HW_ + sg * 8);
            *(uint4*)((char*)sk + r * 144 + sg * 16) =
                *(const uint4*)(ksp + base + (size_t)r * HW_ + sg * 8);
        }
        __syncthreads();

#pragma unroll
        for (int kk = 0; kk < 4; kk++) {
            uint32_t a[4];
            {
                uint32_t row = wid * 16 + (lane & 15);
                uint32_t col = kk * 16 + ((lane >> 4) << 3);
                ldsm4(a, sv_u + (row * 72 + col) * 2);
            }
            uint32_t bf[4][4];
#pragma unroll
            for (int j2 = 0; j2 < 4; j2++) {
                uint32_t row = j2 * 16 + (lane & 7) + ((lane >> 4) << 3);
                uint32_t col = kk * 16 + (((lane >> 3) & 1) << 3);
                ldsm4(bf[j2], sk_u + (row * 72 + col) * 2);
            }
#pragma unroll
            for (int j = 0; j < 8; j++)
                mma16816h(acc[j], a, bf[j >> 1][(j & 1) * 2], bf[j >> 1][(j & 1) * 2 + 1]);
        }
        __syncthreads();
    }

    __half* ap = attnT + ((size_t)((chunk * B_ + b) * NH + h)) * (HD * HD);
    int g = lane >> 2, tg = lane & 3;
#pragma unroll
    for (int j = 0; j < 8; j++)
#pragma unroll
        for (int e = 0; e < 2; e++) {
            int row = wid * 16 + g + e * 8;       // de
            int col = j * 8 + tg * 2;             // dh
            __half2 h2 = __floats2half2_rn(acc[j][e * 2] * 0.0625f,
                                           acc[j][e * 2 + 1] * 0.0625f);
            *(__half2*)(ap + (size_t)row * HD + col) = h2;
        }
}

// ---------------------------------------------------------------------------
// x2 HMMA + LIF(0.5): out[de][n] = sum_dh attnT[de][dh] * qT[n][h*64+dh]
// ---------------------------------------------------------------------------
__global__ void __launch_bounds__(256) x2_hmma_kernel(
    const __half* __restrict__ qT, const __half* __restrict__ attnT,
    __half* __restrict__ x2T)
{
    __shared__ __half sq[128][72];
    __shared__ __half sa[64][72];
    uint32_t sq_u = smem_to_u32(&sq[0][0]);
    uint32_t sa_u = smem_to_u32(&sa[0][0]);

    int nhalf = blockIdx.x, h = blockIdx.y, b = blockIdx.z;
    int tid = threadIdx.x;
    int wid = tid >> 5, lane = tid & 31;
    int wm = wid >> 1, wn = wid & 1;

    float mem[8][4];
#pragma unroll
    for (int j = 0; j < 8; j++)
#pragma unroll
        for (int e = 0; e < 4; e++) mem[j][e] = 0.f;

#pragma unroll
    for (int t = 0; t < T_; t++) {
        if ((t & 1) == 0) {
            int chunk = t >> 1;
            const __half* ap = attnT + ((size_t)((chunk * B_ + b) * NH + h)) * (HD * HD);
#pragma unroll
            for (int l = 0; l < 2; l++) {
                int lin = l * 256 + tid;
                int r = lin >> 3, sg = lin & 7;
                *(uint4*)((char*)sa + r * 144 + sg * 16) =
                    *(const uint4*)(ap + (size_t)r * HD + sg * 8);
            }
        }
        {
            const __half* qp = qT + ((size_t)(t * B_ + b) * HW_ + nhalf * 128) * C_ + h * HD;
#pragma unroll
            for (int l = 0; l < 4; l++) {
                int lin = l * 256 + tid;
                int r = lin >> 3, sg = lin & 7;
                *(uint4*)((char*)sq + r * 144 + sg * 16) =
                    *(const uint4*)(qp + (size_t)r * C_ + sg * 8);
            }
        }
        __syncthreads();

        float acc[8][4];
#pragma unroll
        for (int j = 0; j < 8; j++)
#pragma unroll
            for (int e = 0; e < 4; e++) acc[j][e] = 0.f;

#pragma unroll
        for (int kk = 0; kk < 4; kk++) {
            uint32_t a[4];
            {
                uint32_t row = wm * 16 + (lane & 15);
                uint32_t col = kk * 16 + ((lane >> 4) << 3);
                ldsm4(a, sa_u + (row * 72 + col) * 2);
            }
            uint32_t bf[4][4];
#pragma unroll
            for (int j2 = 0; j2 < 4; j2++) {
                uint32_t row = wn * 64 + j2 * 16 + (lane & 7) + ((lane >> 4) << 3);
                uint32_t col = kk * 16 + (((lane >> 3) & 1) << 3);
                ldsm4(bf[j2], sq_u + (row * 72 + col) * 2);
            }
#pragma unroll
            for (int j = 0; j < 8; j++)
                mma16816h(acc[j], a, bf[j >> 1][(j & 1) * 2], bf[j >> 1][(j & 1) * 2 + 1]);
        }

        int g = lane >> 2, tg = lane & 3;
        size_t obase = ((size_t)(t * B_ + b) * HW_ + nhalf * 128) * C_ + h * HD;
#pragma unroll
        for (int j = 0; j < 8; j++)
#pragma unroll
            for (int e = 0; e < 4; e++) {
                float xv = acc[j][e];
                mem[j][e] = mem[j][e] + (xv - mem[j][e]) * 0.5f;
                float s = (mem[j][e] >= 0.5f) ? 1.0f : 0.0f;
                if (s != 0.f) mem[j][e] = 0.f;
                int n = wn * 64 + j * 8 + tg * 2 + (e & 1);
                int de = wm * 16 + g + ((e >> 1) << 3);
                x2T[obase + (size_t)n * C_ + de] = __float2half(s);
            }
        __syncthreads();
    }
}

// ---------------------------------------------------------------------------
extern "C" void kernel_launch(void* const* d_in, const int* in_sizes, int n_in,
                              void* d_out, int out_size)
{
    const float* x       = (const float*)d_in[0];
    const float* Wq      = (const float*)d_in[1];
    const float* q_scale = (const float*)d_in[2];
    const float* q_bias  = (const float*)d_in[3];
    const float* Wk      = (const float*)d_in[4];
    const float* k_scale = (const float*)d_in[5];
    const float* k_bias  = (const float*)d_in[6];
    const float* Wv      = (const float*)d_in[7];
    const float* v_scale = (const float*)d_in[8];
    const float* v_bias  = (const float*)d_in[9];
    const float* Wp      = (const float*)d_in[10];
    const float* bp      = (const float*)d_in[11];
    const float* p_scale = (const float*)d_in[12];
    const float* p_bias  = (const float*)d_in[13];
    float* out = (float*)d_out;

    __half *xsB, *qT, *ksp, *vsp, *x2T, *attnT, *wsplit;
    float *gscale, *gbias;
    cudaGetSymbolAddress((void**)&xsB,    g_xsB);
    cudaGetSymbolAddress((void**)&qT,     g_qT);
    cudaGetSymbolAddress((void**)&ksp,    g_ks);
    cudaGetSymbolAddress((void**)&vsp,    g_vs);
    cudaGetSymbolAddress((void**)&x2T,    g_x2T);
    cudaGetSymbolAddress((void**)&attnT,  g_attnT);
    cudaGetSymbolAddress((void**)&wsplit, g_wsplit);
    cudaGetSymbolAddress((void**)&gscale, g_scale);
    cudaGetSymbolAddress((void**)&gbias,  g_bias);

    const int SMEM_BYTES = 2 * STAGE_BYTES;   // 73728
    cudaFuncSetAttribute(gemm_hmma_kernel<0>, cudaFuncAttributeMaxDynamicSharedMemorySize, SMEM_BYTES);
    cudaFuncSetAttribute(gemm_hmma_kernel<1>, cudaFuncAttributeMaxDynamicSharedMemorySize, SMEM_BYTES);

    // 0. weight splits (fp16 hi/mid', exact) + scale/bias concat
    wsplit_kernel<<<4096, 256>>>(Wq, Wk, Wv, Wp, wsplit);
    sb_kernel<<<6, 256>>>(q_scale, q_bias, k_scale, k_bias, v_scale, v_bias, gscale, gbias);

    // 1. shortcut LIF + transpose -> xsB [b][n'][c] (t folded into n')
    lif_in_trans_kernel<<<dim3(4, 8, 32), 256>>>(x, xsB);

    // 2. q/k/v conv + BN + LIF fused in GEMM epilogue -> qT/ks/vs + vout
    gemm_hmma_kernel<0><<<dim3(8, 12, 32), 256, SMEM_BYTES>>>(
        wsplit, xsB, qT, ksp, vsp, out + TOTAL,
        gscale, gbias, nullptr, nullptr, nullptr, 0);

    // 3. attnT = (1/16) (k^T v)^T per (chunk, b, h), HMMA fp16 (exact)
    attn_hmma_kernel<<<2 * B_ * NH, 128>>>(ksp, vsp, attnT);

    // 4. x2 = attn^T @ q + LIF(0.5), HMMA fp16, writes x2T fp16 [tb][n][c]
    x2_hmma_kernel<<<dim3(2, NH, B_), 256>>>(qT, attnT, x2T);

    // 5. proj conv (hi split) + BN + identity via HMMA -> out[0 : TOTAL)
    gemm_hmma_kernel<1><<<dim3(2, 4, 128), 256, SMEM_BYTES>>>(
        wsplit, x2T, nullptr, nullptr, nullptr, nullptr,
        p_scale, p_bias, bp, x, out, 1536);
}

// round 10
// speedup vs baseline: 1.4829x; 1.4829x over previous
#include <cuda_runtime.h>
#include <cuda_fp16.h>
#include <cstdint>

// Problem constants
#define T_    4
#define B_    32
#define C_    512
#define HW_   256
#define NH    8
#define HD    64
#define SLICE 4194304      // B*C*HW = one time slice
#define TOTAL 16777216     // T*B*C*HW
#define CN    131072       // C*HW per (t,b)

// ---------------------------------------------------------------------------
// helpers
// ---------------------------------------------------------------------------
__device__ __forceinline__ uint32_t smem_to_u32(const void* smem_ptr) {
    uint32_t addr;
    asm("{ .reg .u64 tmp; cvta.to.shared.u64 tmp, %1; cvt.u32.u64 %0, tmp; }"
        : "=r"(addr) : "l"(smem_ptr));
    return addr;
}

__device__ __forceinline__ void cp16(uint32_t dst, const void* src) {
    asm volatile("cp.async.ca.shared.global [%0], [%1], 16;" :: "r"(dst), "l"(src));
}

__device__ __forceinline__ void ldsm4(uint32_t* r, uint32_t addr) {
    asm volatile("ldmatrix.sync.aligned.m8n8.x4.shared.b16 {%0,%1,%2,%3}, [%4];"
                 : "=r"(r[0]), "=r"(r[1]), "=r"(r[2]), "=r"(r[3]) : "r"(addr));
}

__device__ __forceinline__ void mma16816h(float* c, const uint32_t* a,
                                          uint32_t b0, uint32_t b1) {
    asm volatile(
        "mma.sync.aligned.m16n8k16.row.col.f32.f16.f16.f32 "
        "{%0,%1,%2,%3}, {%4,%5,%6,%7}, {%8,%9}, {%0,%1,%2,%3};"
        : "+f"(c[0]), "+f"(c[1]), "+f"(c[2]), "+f"(c[3])
        : "r"(a[0]), "r"(a[1]), "r"(a[2]), "r"(a[3]), "r"(b0), "r"(b1));
}

// ---------------------------------------------------------------------------
// Scratch (static device globals)
// ---------------------------------------------------------------------------
__device__ __half g_xsB[TOTAL];              // x spikes, per-b matrix [b][n'=0..1023][c]
                                             //   n' = (n>>3)*32 + t*8 + (n&7)
__device__ __half g_qT[TOTAL];               // q spikes, [tb][n][c] fp16
__device__ __half g_ks[TOTAL];               // k spikes, [t,b,c,n] fp16
__device__ __half g_vs[TOTAL];               // v spikes, [t,b,c,n] fp16
__device__ __half g_x2T[TOTAL];              // x2 spikes, [tb][n][c] fp16
__device__ __half g_attnT[2 * B_ * NH * HD * HD];   // [chunk,b,h][de][dh]
__device__ __half g_wsplit[2u * 2048u * 512u];      // [split: 0=mid',1=hi][2048][512]
__device__ float  g_scale[3 * C_];
__device__ float  g_bias [3 * C_];

// ---------------------------------------------------------------------------
// Prep: exact 2-way fp16 split of the 4 weight matrices
//   w = hi + mid' * 2^-12   (mid' = fp16(r1*4096))
// ---------------------------------------------------------------------------
__global__ void wsplit_kernel(const float* __restrict__ Wq, const float* __restrict__ Wk,
                              const float* __restrict__ Wv, const float* __restrict__ Wp,
                              __half* __restrict__ ws)
{
    int i = blockIdx.x * 256 + threadIdx.x;      // 0 .. 2048*512-1
    int r = i >> 9;
    int kk = i & 511;
    const float* W = (r < 512) ? Wq : (r < 1024) ? Wk : (r < 1536) ? Wv : Wp;
    float w = W[(size_t)(r & 511) * 512 + kk];
    __half hi = __float2half_rn(w);
    float r1 = w - __half2float(hi);
    __half mid = __float2half_rn(r1 * 4096.0f);
    ws[i]            = mid;     // split 0 = scaled mid (accumulated first)
    ws[1048576u + i] = hi;      // split 1 = hi
}

__global__ void sb_kernel(const float* __restrict__ qs, const float* __restrict__ qb,
                          const float* __restrict__ ks, const float* __restrict__ kb,
                          const float* __restrict__ vs, const float* __restrict__ vb,
                          float* __restrict__ gs, float* __restrict__ gb)
{
    int i = blockIdx.x * 256 + threadIdx.x;
    if (i >= 1536) return;
    if (i < 512)       { gs[i] = qs[i];        gb[i] = qb[i]; }
    else if (i < 1024) { gs[i] = ks[i - 512];  gb[i] = kb[i - 512]; }
    else               { gs[i] = vs[i - 1024]; gb[i] = vb[i - 1024]; }
}

// ---------------------------------------------------------------------------
// K1: shortcut LIF on x fused with transpose -> xsB fp16 [b][n'][c]
//   n' = (n>>3)*32 + t*8 + (n&7)   (t folded into the GEMM N dimension)
// ---------------------------------------------------------------------------
__global__ void lif_in_trans_kernel(const float* __restrict__ x,
                                    __half* __restrict__ xsB)
{
    __shared__ __half tile[64][65];
    int nblk = blockIdx.x, cblk = blockIdx.y, b = blockIdx.z;
    int tid = threadIdx.x;

    float v[16];
#pragma unroll
    for (int p = 0; p < 16; p++) v[p] = 0.f;

    __half* D = xsB + (size_t)b * (1024 * 512);

#pragma unroll
    for (int t = 0; t < T_; t++) {
        if (t) __syncthreads();
#pragma unroll
        for (int p = 0; p < 16; p++) {
            int c_l = p * 4 + (tid >> 6), n_l = tid & 63;
            float xv = x[(size_t)t * SLICE +
                         ((size_t)(b * C_ + cblk * 64 + c_l)) * HW_ + nblk * 64 + n_l];
            v[p] = v[p] + (xv - v[p]) * 0.5f;
            float s = (v[p] >= 1.0f) ? 1.0f : 0.0f;
            if (s != 0.f) v[p] = 0.f;
            tile[c_l][n_l] = __float2half(s);
        }
        __syncthreads();
#pragma unroll
        for (int p = 0; p < 16; p++) {
            int c_l = tid & 63, n_l = p * 4 + (tid >> 6);
            int n = nblk * 64 + n_l;
            int nprime = (n >> 3) * 32 + t * 8 + (n & 7);
            D[(size_t)nprime * C_ + cblk * 64 + c_l] = tile[c_l][n_l];
        }
    }
}

// ---------------------------------------------------------------------------
// HMMA GEMM: CTA 128x128, 2x4 warps of 64x32, TWO-stage double buffer (r6 loop)
// MODE 0: qkv. B = xsB per b (1024 rows, t folded: jj index == t). 16 stages
//         (8 mid' + 8 hi, exact). Epilogue: BN -> LIF(vth=1) -> qT/ks/vs/vout.
//         grid (8 nblk, 12 mtile, 32 b)
// MODE 1: proj, hi-split ONLY (8 stages). Epilogue: (acc+cb)*sc+bi+identity.
//         grid (2 ntile, 4 mtile, 128 tb)
// ---------------------------------------------------------------------------
#define STAGE_BYTES 36864
#define A_BYTES     18432
#define SM_STRIDE   136          // halves; 272B row stride

template<int MODE>
__global__ void __launch_bounds__(256, 2) gemm_hmma_kernel(
    const __half* __restrict__ wsplit,            // [2][2048][512]
    const __half* __restrict__ Bmat,              // MODE0: xsB ; MODE1: x2T
    __half* __restrict__ qT, __half* __restrict__ ksp, __half* __restrict__ vsp,
    float* __restrict__ vout,
    const float* __restrict__ scale, const float* __restrict__ bias,
    const float* __restrict__ cbias, const float* __restrict__ identity,
    float* __restrict__ outp, int wrow_base)
{
    constexpr int NS = (MODE == 0) ? 16 : 8;
    extern __shared__ __align__(128) char smem[];
    uint32_t smem_u = smem_to_u32(smem);
    const int tid = threadIdx.x;
    const int wid = tid >> 5, lane = tid & 31;
    const int wm = wid >> 2, wn = wid & 3;         // 2 x 4 warp grid, 64x32 tiles
    const int n0 = blockIdx.x * 128;
    const int m0 = blockIdx.y * 128;
    const int bz = blockIdx.z;
    const char* Bbase = (MODE == 0)
        ? (const char*)(Bmat + (size_t)bz * (1024 * 512))
        : (const char*)(Bmat + (size_t)bz * CN);

    float acc[4][4][4];
#pragma unroll
    for (int i = 0; i < 4; i++)
#pragma unroll
        for (int j = 0; j < 4; j++)
#pragma unroll
            for (int e = 0; e < 4; e++) acc[i][j][e] = 0.f;

    auto cp_stage = [&](int s) {
        int buf = s & 1;
        int split = (MODE == 0) ? (s >> 3) : 1;   // MODE1: hi only
        int kA = (s & 7) << 6;
        const char* Ag = (const char*)wsplit
                       + ((size_t)split * 2048 + (size_t)(wrow_base + m0)) * 1024
                       + (size_t)kA * 2;
        const char* Bg = Bbase + (size_t)n0 * 1024 + (size_t)kA * 2;
        uint32_t sA = smem_u + buf * STAGE_BYTES;
        uint32_t sB = sA + A_BYTES;
#pragma unroll
        for (int p = 0; p < 4; p++) {
            int lin = p * 256 + tid;
            int r = lin >> 3, sg = lin & 7;
            cp16(sA + r * 144 + sg * 16, Ag + (size_t)r * 1024 + sg * 16);
            cp16(sB + r * 144 + sg * 16, Bg + (size_t)r * 1024 + sg * 16);
        }
        asm volatile("cp.async.commit_group;");
    };

    cp_stage(0);

    for (int s = 0; s < NS; s++) {
        if (s + 1 < NS) {
            cp_stage(s + 1);
            asm volatile("cp.async.wait_group 1;");
        } else {
            asm volatile("cp.async.wait_group 0;");
        }
        __syncthreads();

        uint32_t sA = smem_u + (s & 1) * STAGE_BYTES;
        uint32_t sB = sA + A_BYTES;

#pragma unroll
        for (int kk = 0; kk < 4; kk++) {
            uint32_t a[4][4];
#pragma unroll
            for (int i = 0; i < 4; i++) {
                uint32_t row = wm * 64 + i * 16 + (lane & 15);
                uint32_t col = kk * 16 + ((lane >> 4) << 3);
                ldsm4(a[i], sA + (row * 72 + col) * 2);
            }
            uint32_t bf[2][4];
#pragma unroll
            for (int j2 = 0; j2 < 2; j2++) {
                uint32_t row = wn * 32 + j2 * 16 + (lane & 7) + ((lane >> 4) << 3);
                uint32_t col = kk * 16 + (((lane >> 3) & 1) << 3);
                ldsm4(bf[j2], sB + (row * 72 + col) * 2);
            }
#pragma unroll
            for (int i = 0; i < 4; i++)
#pragma unroll
                for (int jj = 0; jj < 4; jj++) {
                    uint32_t b0 = bf[jj >> 1][(jj & 1) * 2 + 0];
                    uint32_t b1 = bf[jj >> 1][(jj & 1) * 2 + 1];
                    mma16816h(acc[i][jj], a[i], b0, b1);
                }
        }
        if (MODE == 0 && s == 7) {
            // fold the scaled mid split: acc *= 2^-12 (exact)
#pragma unroll
            for (int i = 0; i < 4; i++)
#pragma unroll
                for (int j = 0; j < 4; j++)
#pragma unroll
                    for (int e = 0; e < 4; e++) acc[i][j][e] *= 0.000244140625f;
        }
        __syncthreads();
    }

    int g = lane >> 2, tg = lane & 3;

    if (MODE == 0) {
        // ---- BN + LIF (vth=1) in registers: jj == t ----
        __half (*sm)[SM_STRIDE] = (__half(*)[SM_STRIDE])smem;
#pragma unroll
        for (int i = 0; i < 4; i++) {
#pragma unroll
            for (int eh = 0; eh < 2; eh++) {
                int rl = wm * 64 + i * 16 + g + eh * 8;
                float sc = scale[m0 + rl], bi = bias[m0 + rl];
#pragma unroll
                for (int e1 = 0; e1 < 2; e1++) {
                    int nl = wn * 8 + 2 * tg + e1;        // n_local 0..31
                    float v = 0.f;
#pragma unroll
                    for (int t = 0; t < T_; t++) {
                        float xv = acc[i][t][eh * 2 + e1] * sc + bi;
                        v = v + (xv - v) * 0.5f;
                        float ss = (v >= 1.0f) ? 1.0f : 0.0f;
                        if (ss != 0.f) v = 0.f;
                        sm[rl][t * 32 + nl] = __float2half(ss);
                    }
                }
            }
        }
        __syncthreads();

        int tt   = blockIdx.y >> 2;      // 0 q, 1 k, 2 v
        int msub = blockIdx.y & 3;       // 128-row block within tensor
        int b    = bz;
        int nb   = blockIdx.x;           // n base = nb*32

        if (tt == 0) {
            // qT[(t*32+b)*256 + nb*32 + n][msub*128 + half*64 + c]
            int rid = tid >> 1, half = tid & 1;
            int t = rid >> 5, n = rid & 31;
            __half tmp[64];
#pragma unroll
            for (int c = 0; c < 64; c++) tmp[c] = sm[half * 64 + c][t * 32 + n];
            __half* dst = qT + ((size_t)((t * 32 + b) * 256 + nb * 32 + n)) * 512
                             + msub * 128 + half * 64;
#pragma unroll
            for (int u = 0; u < 8; u++) ((uint4*)dst)[u] = ((uint4*)tmp)[u];
        } else {
            __half* base = (tt == 1) ? ksp : vsp;
#pragma unroll
            for (int p = 0; p < 2; p++) {
                int rid = p * 256 + tid;       // 0..511
                int t = rid >> 7, cl = rid & 127;
                const uint4* srow = (const uint4*)&sm[cl][t * 32];
                __half* dst = base + (size_t)t * SLICE
                            + ((size_t)(b * C_ + msub * 128 + cl)) * HW_ + nb * 32;
#pragma unroll
                for (int u = 0; u < 4; u++) ((uint4*)dst)[u] = srow[u];
            }
            if (tt == 2) {
                // vout fp32 [t,b,h,n,hd]
                int t = tid >> 6, rem = tid & 63;
                int hl = rem >> 5, n = rem & 31;
                int h = msub * 2 + hl;
                float* dst = vout + ((((size_t)(t * 32 + b) * NH + h) * HW_) + nb * 32 + n) * HD;
#pragma unroll
                for (int c4 = 0; c4 < 16; c4++) {
                    float4 f;
                    f.x = __half2float(sm[hl * 64 + c4 * 4 + 0][t * 32 + n]);
                    f.y = __half2float(sm[hl * 64 + c4 * 4 + 1][t * 32 + n]);
                    f.z = __half2float(sm[hl * 64 + c4 * 4 + 2][t * 32 + n]);
                    f.w = __half2float(sm[hl * 64 + c4 * 4 + 3][t * 32 + n]);
                    ((float4*)dst)[c4] = f;
                }
            }
        }
    } else {
        // ---- proj epilogue ----
#pragma unroll
        for (int i = 0; i < 4; i++) {
            int mloc = m0 + wm * 64 + i * 16 + g;
#pragma unroll
            for (int half = 0; half < 2; half++) {
                int c = mloc + half * 8;
                float sc = scale[c], bi = bias[c], cb = cbias[c];
                float* dst = outp + (size_t)bz * CN + (size_t)c * HW_;
                const float* idp = identity + (size_t)bz * CN + (size_t)c * HW_;
#pragma unroll
                for (int jj = 0; jj < 4; jj++) {
                    int col = n0 + wn * 32 + jj * 8 + 2 * tg;
                    float2 id2 = *(const float2*)&idp[col];
                    float2 v2;
                    v2.x = (acc[i][jj][half * 2 + 0] + cb) * sc + bi + id2.x;
                    v2.y = (acc[i][jj][half * 2 + 1] + cb) * sc + bi + id2.y;
                    *(float2*)&dst[col] = v2;
                }
            }
        }
    }
}

// ---------------------------------------------------------------------------
// attn HMMA: attnT[chunk,b,h][de][dh] = (1/16) * sum_{t in chunk, s} v[de,s]*k[dh,s]
// ---------------------------------------------------------------------------
__global__ void __launch_bounds__(128) attn_hmma_kernel(
    const __half* __restrict__ ksp, const __half* __restrict__ vsp,
    __half* __restrict__ attnT)
{
    __shared__ __half sv[64][72];
    __shared__ __half sk[64][72];
    uint32_t sv_u = smem_to_u32(&sv[0][0]);
    uint32_t sk_u = smem_to_u32(&sk[0][0]);

    int cbh = blockIdx.x;
    int h = cbh & 7, b = (cbh >> 3) & 31, chunk = cbh >> 8;
    int tid = threadIdx.x;
    int wid = tid >> 5, lane = tid & 31;

    float acc[8][4];
#pragma unroll
    for (int j = 0; j < 8; j++)
#pragma unroll
        for (int e = 0; e < 4; e++) acc[j][e] = 0.f;

    for (int st = 0; st < 8; st++) {
        int t = chunk * 2 + (st >> 2);
        int n0 = (st & 3) * 64;
        size_t base = (size_t)t * SLICE + ((size_t)(b * C_ + h * HD)) * HW_ + n0;
#pragma unroll
        for (int l = 0; l < 4; l++) {
            int lin = l * 128 + tid;
            int r = lin >> 3, sg = lin & 7;
            *(uint4*)((char*)sv + r * 144 + sg * 16) =
                *(const uint4*)(vsp + base + (size_t)r * HW_ + sg * 8);
            *(uint4*)((char*)sk + r * 144 + sg * 16) =
                *(const uint4*)(ksp + base + (size_t)r * HW_ + sg * 8);
        }
        __syncthreads();

#pragma unroll
        for (int kk = 0; kk < 4; kk++) {
            uint32_t a[4];
            {
                uint32_t row = wid * 16 + (lane & 15);
                uint32_t col = kk * 16 + ((lane >> 4) << 3);
                ldsm4(a, sv_u + (row * 72 + col) * 2);
            }
            uint32_t bf[4][4];
#pragma unroll
            for (int j2 = 0; j2 < 4; j2++) {
                uint32_t row = j2 * 16 + (lane & 7) + ((lane >> 4) << 3);
                uint32_t col = kk * 16 + (((lane >> 3) & 1) << 3);
                ldsm4(bf[j2], sk_u + (row * 72 + col) * 2);
            }
#pragma unroll
            for (int j = 0; j < 8; j++)
                mma16816h(acc[j], a, bf[j >> 1][(j & 1) * 2], bf[j >> 1][(j & 1) * 2 + 1]);
        }
        __syncthreads();
    }

    __half* ap = attnT + ((size_t)((chunk * B_ + b) * NH + h)) * (HD * HD);
    int g = lane >> 2, tg = lane & 3;
#pragma unroll
    for (int j = 0; j < 8; j++)
#pragma unroll
        for (int e = 0; e < 2; e++) {
            int row = wid * 16 + g + e * 8;       // de
            int col = j * 8 + tg * 2;             // dh
            __half2 h2 = __floats2half2_rn(acc[j][e * 2] * 0.0625f,
                                           acc[j][e * 2 + 1] * 0.0625f);
            *(__half2*)(ap + (size_t)row * HD + col) = h2;
        }
}

// ---------------------------------------------------------------------------
// x2 HMMA + LIF(0.5): out[de][n] = sum_dh attnT[de][dh] * qT[n][h*64+dh]
// ---------------------------------------------------------------------------
__global__ void __launch_bounds__(256) x2_hmma_kernel(
    const __half* __restrict__ qT, const __half* __restrict__ attnT,
    __half* __restrict__ x2T)
{
    __shared__ __half sq[128][72];
    __shared__ __half sa[64][72];
    uint32_t sq_u = smem_to_u32(&sq[0][0]);
    uint32_t sa_u = smem_to_u32(&sa[0][0]);

    int nhalf = blockIdx.x, h = blockIdx.y, b = blockIdx.z;
    int tid = threadIdx.x;
    int wid = tid >> 5, lane = tid & 31;
    int wm = wid >> 1, wn = wid & 1;

    float mem[8][4];
#pragma unroll
    for (int j = 0; j < 8; j++)
#pragma unroll
        for (int e = 0; e < 4; e++) mem[j][e] = 0.f;

#pragma unroll
    for (int t = 0; t < T_; t++) {
        if ((t & 1) == 0) {
            int chunk = t >> 1;
            const __half* ap = attnT + ((size_t)((chunk * B_ + b) * NH + h)) * (HD * HD);
#pragma unroll
            for (int l = 0; l < 2; l++) {
                int lin = l * 256 + tid;
                int r = lin >> 3, sg = lin & 7;
                *(uint4*)((char*)sa + r * 144 + sg * 16) =
                    *(const uint4*)(ap + (size_t)r * HD + sg * 8);
            }
        }
        {
            const __half* qp = qT + ((size_t)(t * B_ + b) * HW_ + nhalf * 128) * C_ + h * HD;
#pragma unroll
            for (int l = 0; l < 4; l++) {
                int lin = l * 256 + tid;
                int r = lin >> 3, sg = lin & 7;
                *(uint4*)((char*)sq + r * 144 + sg * 16) =
                    *(const uint4*)(qp + (size_t)r * C_ + sg * 8);
            }
        }
        __syncthreads();

        float acc[8][4];
#pragma unroll
        for (int j = 0; j < 8; j++)
#pragma unroll
            for (int e = 0; e < 4; e++) acc[j][e] = 0.f;

#pragma unroll
        for (int kk = 0; kk < 4; kk++) {
            uint32_t a[4];
            {
                uint32_t row = wm * 16 + (lane & 15);
                uint32_t col = kk * 16 + ((lane >> 4) << 3);
                ldsm4(a, sa_u + (row * 72 + col) * 2);
            }
            uint32_t bf[4][4];
#pragma unroll
            for (int j2 = 0; j2 < 4; j2++) {
                uint32_t row = wn * 64 + j2 * 16 + (lane & 7) + ((lane >> 4) << 3);
                uint32_t col = kk * 16 + (((lane >> 3) & 1) << 3);
                ldsm4(bf[j2], sq_u + (row * 72 + col) * 2);
            }
#pragma unroll
            for (int j = 0; j < 8; j++)
                mma16816h(acc[j], a, bf[j >> 1][(j & 1) * 2], bf[j >> 1][(j & 1) * 2 + 1]);
        }

        int g = lane >> 2, tg = lane & 3;
        size_t obase = ((size_t)(t * B_ + b) * HW_ + nhalf * 128) * C_ + h * HD;
#pragma unroll
        for (int j = 0; j < 8; j++)
#pragma unroll
            for (int e = 0; e < 4; e++) {
                float xv = acc[j][e];
                mem[j][e] = mem[j][e] + (xv - mem[j][e]) * 0.5f;
                float s = (mem[j][e] >= 0.5f) ? 1.0f : 0.0f;
                if (s != 0.f) mem[j][e] = 0.f;
                int n = wn * 64 + j * 8 + tg * 2 + (e & 1);
                int de = wm * 16 + g + ((e >> 1) << 3);
                x2T[obase + (size_t)n * C_ + de] = __float2half(s);
            }
        __syncthreads();
    }
}

// ---------------------------------------------------------------------------
extern "C" void kernel_launch(void* const* d_in, const int* in_sizes, int n_in,
                              void* d_out, int out_size)
{
    const float* x       = (const float*)d_in[0];
    const float* Wq      = (const float*)d_in[1];
    const float* q_scale = (const float*)d_in[2];
    const float* q_bias  = (const float*)d_in[3];
    const float* Wk      = (const float*)d_in[4];
    const float* k_scale = (const float*)d_in[5];
    const float* k_bias  = (const float*)d_in[6];
    const float* Wv      = (const float*)d_in[7];
    const float* v_scale = (const float*)d_in[8];
    const float* v_bias  = (const float*)d_in[9];
    const float* Wp      = (const float*)d_in[10];
    const float* bp      = (const float*)d_in[11];
    const float* p_scale = (const float*)d_in[12];
    const float* p_bias  = (const float*)d_in[13];
    float* out = (float*)d_out;

    __half *xsB, *qT, *ksp, *vsp, *x2T, *attnT, *wsplit;
    float *gscale, *gbias;
    cudaGetSymbolAddress((void**)&xsB,    g_xsB);
    cudaGetSymbolAddress((void**)&qT,     g_qT);
    cudaGetSymbolAddress((void**)&ksp,    g_ks);
    cudaGetSymbolAddress((void**)&vsp,    g_vs);
    cudaGetSymbolAddress((void**)&x2T,    g_x2T);
    cudaGetSymbolAddress((void**)&attnT,  g_attnT);
    cudaGetSymbolAddress((void**)&wsplit, g_wsplit);
    cudaGetSymbolAddress((void**)&gscale, g_scale);
    cudaGetSymbolAddress((void**)&gbias,  g_bias);

    const int SMEM_BYTES = 2 * STAGE_BYTES;   // 73728
    cudaFuncSetAttribute(gemm_hmma_kernel<0>, cudaFuncAttributeMaxDynamicSharedMemorySize, SMEM_BYTES);
    cudaFuncSetAttribute(gemm_hmma_kernel<1>, cudaFuncAttributeMaxDynamicSharedMemorySize, SMEM_BYTES);

    // 0. weight splits (fp16 hi/mid', exact) + scale/bias concat
    wsplit_kernel<<<4096, 256>>>(Wq, Wk, Wv, Wp, wsplit);
    sb_kernel<<<6, 256>>>(q_scale, q_bias, k_scale, k_bias, v_scale, v_bias, gscale, gbias);

    // 1. shortcut LIF + transpose -> xsB [b][n'][c] (t folded into n')
    lif_in_trans_kernel<<<dim3(4, 8, 32), 256>>>(x, xsB);

    // 2. q/k/v conv + BN + LIF fused in GEMM epilogue -> qT/ks/vs + vout
    gemm_hmma_kernel<0><<<dim3(8, 12, 32), 256, SMEM_BYTES>>>(
        wsplit, xsB, qT, ksp, vsp, out + TOTAL,
        gscale, gbias, nullptr, nullptr, nullptr, 0);

    // 3. attnT = (1/16) (k^T v)^T per (chunk, b, h), HMMA fp16 (exact)
    attn_hmma_kernel<<<2 * B_ * NH, 128>>>(ksp, vsp, attnT);

    // 4. x2 = attn^T @ q + LIF(0.5), HMMA fp16, writes x2T fp16 [tb][n][c]
    x2_hmma_kernel<<<dim3(2, NH, B_), 256>>>(qT, attnT, x2T);

    // 5. proj conv (hi split) + BN + identity via HMMA -> out[0 : TOTAL)
    gemm_hmma_kernel<1><<<dim3(2, 4, 128), 256, SMEM_BYTES>>>(
        wsplit, x2T, nullptr, nullptr, nullptr, nullptr,
        p_scale, p_bias, bp, x, out, 1536);
}

// round 11
// speedup vs baseline: 1.5056x; 1.0153x over previous
#include <cuda_runtime.h>
#include <cuda_fp16.h>
#include <cstdint>

// Problem constants
#define T_    4
#define B_    32
#define C_    512
#define HW_   256
#define NH    8
#define HD    64
#define SLICE 4194304      // B*C*HW = one time slice
#define TOTAL 16777216     // T*B*C*HW
#define CN    131072       // C*HW per (t,b)

// ---------------------------------------------------------------------------
// helpers
// ---------------------------------------------------------------------------
__device__ __forceinline__ uint32_t smem_to_u32(const void* smem_ptr) {
    uint32_t addr;
    asm("{ .reg .u64 tmp; cvta.to.shared.u64 tmp, %1; cvt.u32.u64 %0, tmp; }"
        : "=r"(addr) : "l"(smem_ptr));
    return addr;
}

__device__ __forceinline__ void cp16(uint32_t dst, const void* src) {
    asm volatile("cp.async.ca.shared.global [%0], [%1], 16;" :: "r"(dst), "l"(src));
}

__device__ __forceinline__ void ldsm4(uint32_t* r, uint32_t addr) {
    asm volatile("ldmatrix.sync.aligned.m8n8.x4.shared.b16 {%0,%1,%2,%3}, [%4];"
                 : "=r"(r[0]), "=r"(r[1]), "=r"(r[2]), "=r"(r[3]) : "r"(addr));
}

__device__ __forceinline__ void ldsm4t(uint32_t* r, uint32_t addr) {
    asm volatile("ldmatrix.sync.aligned.m8n8.x4.trans.shared.b16 {%0,%1,%2,%3}, [%4];"
                 : "=r"(r[0]), "=r"(r[1]), "=r"(r[2]), "=r"(r[3]) : "r"(addr));
}

__device__ __forceinline__ void mma16816h(float* c, const uint32_t* a,
                                          uint32_t b0, uint32_t b1) {
    asm volatile(
        "mma.sync.aligned.m16n8k16.row.col.f32.f16.f16.f32 "
        "{%0,%1,%2,%3}, {%4,%5,%6,%7}, {%8,%9}, {%0,%1,%2,%3};"
        : "+f"(c[0]), "+f"(c[1]), "+f"(c[2]), "+f"(c[3])
        : "r"(a[0]), "r"(a[1]), "r"(a[2]), "r"(a[3]), "r"(b0), "r"(b1));
}

// ---------------------------------------------------------------------------
// Scratch (static device globals)
// ---------------------------------------------------------------------------
__device__ __half g_xsB[TOTAL];              // x spikes, per-b matrix [b][n'=0..1023][c]
__device__ __half g_qs[TOTAL];               // q spikes, [t,b,c,n] fp16
__device__ __half g_ks[TOTAL];               // k spikes, [t,b,c,n] fp16
__device__ __half g_vs[TOTAL];               // v spikes, [t,b,c,n] fp16
__device__ __half g_x2T[TOTAL];              // x2 spikes, [tb][n][c] fp16
__device__ __half g_attnT[2 * B_ * NH * HD * HD];   // [chunk,b,h][de][dh]
__device__ __half g_wsplit[2u * 2048u * 512u];      // [split: 0=mid',1=hi][2048][512]
__device__ float  g_scale[3 * C_];
__device__ float  g_bias [3 * C_];

// ---------------------------------------------------------------------------
// Prep: exact 2-way fp16 split of the 4 weight matrices
// ---------------------------------------------------------------------------
__global__ void wsplit_kernel(const float* __restrict__ Wq, const float* __restrict__ Wk,
                              const float* __restrict__ Wv, const float* __restrict__ Wp,
                              __half* __restrict__ ws)
{
    int i = blockIdx.x * 256 + threadIdx.x;      // 0 .. 2048*512-1
    int r = i >> 9;
    int kk = i & 511;
    const float* W = (r < 512) ? Wq : (r < 1024) ? Wk : (r < 1536) ? Wv : Wp;
    float w = W[(size_t)(r & 511) * 512 + kk];
    __half hi = __float2half_rn(w);
    float r1 = w - __half2float(hi);
    __half mid = __float2half_rn(r1 * 4096.0f);
    ws[i]            = mid;
    ws[1048576u + i] = hi;
}

__global__ void sb_kernel(const float* __restrict__ qs, const float* __restrict__ qb,
                          const float* __restrict__ ks, const float* __restrict__ kb,
                          const float* __restrict__ vs, const float* __restrict__ vb,
                          float* __restrict__ gs, float* __restrict__ gb)
{
    int i = blockIdx.x * 256 + threadIdx.x;
    if (i >= 1536) return;
    if (i < 512)       { gs[i] = qs[i];        gb[i] = qb[i]; }
    else if (i < 1024) { gs[i] = ks[i - 512];  gb[i] = kb[i - 512]; }
    else               { gs[i] = vs[i - 1024]; gb[i] = vb[i - 1024]; }
}

// ---------------------------------------------------------------------------
// K1: shortcut LIF on x fused with transpose -> xsB fp16 [b][n'][c]
//   n' = (n>>3)*32 + t*8 + (n&7)
// ---------------------------------------------------------------------------
__global__ void lif_in_trans_kernel(const float* __restrict__ x,
                                    __half* __restrict__ xsB)
{
    __shared__ __half tile[64][65];
    int nblk = blockIdx.x, cblk = blockIdx.y, b = blockIdx.z;
    int tid = threadIdx.x;

    float v[16];
#pragma unroll
    for (int p = 0; p < 16; p++) v[p] = 0.f;

    __half* D = xsB + (size_t)b * (1024 * 512);

#pragma unroll
    for (int t = 0; t < T_; t++) {
        if (t) __syncthreads();
#pragma unroll
        for (int p = 0; p < 16; p++) {
            int c_l = p * 4 + (tid >> 6), n_l = tid & 63;
            float xv = x[(size_t)t * SLICE +
                         ((size_t)(b * C_ + cblk * 64 + c_l)) * HW_ + nblk * 64 + n_l];
            v[p] = v[p] + (xv - v[p]) * 0.5f;
            float s = (v[p] >= 1.0f) ? 1.0f : 0.0f;
            if (s != 0.f) v[p] = 0.f;
            tile[c_l][n_l] = __float2half(s);
        }
        __syncthreads();
#pragma unroll
        for (int p = 0; p < 16; p++) {
            int c_l = tid & 63, n_l = p * 4 + (tid >> 6);
            int n = nblk * 64 + n_l;
            int nprime = (n >> 3) * 32 + t * 8 + (n & 7);
            D[(size_t)nprime * C_ + cblk * 64 + c_l] = tile[c_l][n_l];
        }
    }
}

// ---------------------------------------------------------------------------
// HMMA GEMM: CTA 128x128, 2x4 warps of 64x32, TWO-stage double buffer
// MODE 0: qkv, 16 stages (8 mid' + 8 hi, exact). Epilogue: BN -> LIF(vth=1)
//         -> q/k/v all in [t,b,c,n] (+ vout fp32). grid (8 nblk, 12 mtile, 32 b)
// MODE 1: proj, hi-split ONLY (8 stages). grid (2 ntile, 4 mtile, 128 tb)
// ---------------------------------------------------------------------------
#define STAGE_BYTES 36864
#define A_BYTES     18432
#define SM_STRIDE   136          // halves; 272B row stride

template<int MODE>
__global__ void __launch_bounds__(256, 2) gemm_hmma_kernel(
    const __half* __restrict__ wsplit,            // [2][2048][512]
    const __half* __restrict__ Bmat,              // MODE0: xsB ; MODE1: x2T
    __half* __restrict__ qsp, __half* __restrict__ ksp, __half* __restrict__ vsp,
    float* __restrict__ vout,
    const float* __restrict__ scale, const float* __restrict__ bias,
    const float* __restrict__ cbias, const float* __restrict__ identity,
    float* __restrict__ outp, int wrow_base)
{
    constexpr int NS = (MODE == 0) ? 16 : 8;
    extern __shared__ __align__(128) char smem[];
    uint32_t smem_u = smem_to_u32(smem);
    const int tid = threadIdx.x;
    const int wid = tid >> 5, lane = tid & 31;
    const int wm = wid >> 2, wn = wid & 3;         // 2 x 4 warp grid, 64x32 tiles
    const int n0 = blockIdx.x * 128;
    const int m0 = blockIdx.y * 128;
    const int bz = blockIdx.z;
    const char* Bbase = (MODE == 0)
        ? (const char*)(Bmat + (size_t)bz * (1024 * 512))
        : (const char*)(Bmat + (size_t)bz * CN);

    float acc[4][4][4];
#pragma unroll
    for (int i = 0; i < 4; i++)
#pragma unroll
        for (int j = 0; j < 4; j++)
#pragma unroll
            for (int e = 0; e < 4; e++) acc[i][j][e] = 0.f;

    auto cp_stage = [&](int s) {
        int buf = s & 1;
        int split = (MODE == 0) ? (s >> 3) : 1;   // MODE1: hi only
        int kA = (s & 7) << 6;
        const char* Ag = (const char*)wsplit
                       + ((size_t)split * 2048 + (size_t)(wrow_base + m0)) * 1024
                       + (size_t)kA * 2;
        const char* Bg = Bbase + (size_t)n0 * 1024 + (size_t)kA * 2;
        uint32_t sA = smem_u + buf * STAGE_BYTES;
        uint32_t sB = sA + A_BYTES;
#pragma unroll
        for (int p = 0; p < 4; p++) {
            int lin = p * 256 + tid;
            int r = lin >> 3, sg = lin & 7;
            cp16(sA + r * 144 + sg * 16, Ag + (size_t)r * 1024 + sg * 16);
            cp16(sB + r * 144 + sg * 16, Bg + (size_t)r * 1024 + sg * 16);
        }
        asm volatile("cp.async.commit_group;");
    };

    cp_stage(0);

    for (int s = 0; s < NS; s++) {
        if (s + 1 < NS) {
            cp_stage(s + 1);
            asm volatile("cp.async.wait_group 1;");
        } else {
            asm volatile("cp.async.wait_group 0;");
        }
        __syncthreads();

        uint32_t sA = smem_u + (s & 1) * STAGE_BYTES;
        uint32_t sB = sA + A_BYTES;

#pragma unroll
        for (int kk = 0; kk < 4; kk++) {
            uint32_t a[4][4];
#pragma unroll
            for (int i = 0; i < 4; i++) {
                uint32_t row = wm * 64 + i * 16 + (lane & 15);
                uint32_t col = kk * 16 + ((lane >> 4) << 3);
                ldsm4(a[i], sA + (row * 72 + col) * 2);
            }
            uint32_t bf[2][4];
#pragma unroll
            for (int j2 = 0; j2 < 2; j2++) {
                uint32_t row = wn * 32 + j2 * 16 + (lane & 7) + ((lane >> 4) << 3);
                uint32_t col = kk * 16 + (((lane >> 3) & 1) << 3);
                ldsm4(bf[j2], sB + (row * 72 + col) * 2);
            }
#pragma unroll
            for (int i = 0; i < 4; i++)
#pragma unroll
                for (int jj = 0; jj < 4; jj++) {
                    uint32_t b0 = bf[jj >> 1][(jj & 1) * 2 + 0];
                    uint32_t b1 = bf[jj >> 1][(jj & 1) * 2 + 1];
                    mma16816h(acc[i][jj], a[i], b0, b1);
                }
        }
        if (MODE == 0 && s == 7) {
#pragma unroll
            for (int i = 0; i < 4; i++)
#pragma unroll
                for (int j = 0; j < 4; j++)
#pragma unroll
                    for (int e = 0; e < 4; e++) acc[i][j][e] *= 0.000244140625f;
        }
        __syncthreads();
    }

    int g = lane >> 2, tg = lane & 3;

    if (MODE == 0) {
        // ---- BN + LIF (vth=1) in registers: jj == t ----
        __half (*sm)[SM_STRIDE] = (__half(*)[SM_STRIDE])smem;
#pragma unroll
        for (int i = 0; i < 4; i++) {
#pragma unroll
            for (int eh = 0; eh < 2; eh++) {
                int rl = wm * 64 + i * 16 + g + eh * 8;
                float sc = scale[m0 + rl], bi = bias[m0 + rl];
#pragma unroll
                for (int e1 = 0; e1 < 2; e1++) {
                    int nl = wn * 8 + 2 * tg + e1;        // n_local 0..31
                    float v = 0.f;
#pragma unroll
                    for (int t = 0; t < T_; t++) {
                        float xv = acc[i][t][eh * 2 + e1] * sc + bi;
                        v = v + (xv - v) * 0.5f;
                        float ss = (v >= 1.0f) ? 1.0f : 0.0f;
                        if (ss != 0.f) v = 0.f;
                        sm[rl][t * 32 + nl] = __float2half(ss);
                    }
                }
            }
        }
        __syncthreads();

        int tt   = blockIdx.y >> 2;      // 0 q, 1 k, 2 v
        int msub = blockIdx.y & 3;       // 128-row block within tensor
        int b    = bz;
        int nb   = blockIdx.x;           // n base = nb*32

        __half* base = (tt == 0) ? qsp : (tt == 1) ? ksp : vsp;
#pragma unroll
        for (int p = 0; p < 2; p++) {
            int rid = p * 256 + tid;       // 0..511
            int t = rid >> 7, cl = rid & 127;
            const uint4* srow = (const uint4*)&sm[cl][t * 32];
            __half* dst = base + (size_t)t * SLICE
                        + ((size_t)(b * C_ + msub * 128 + cl)) * HW_ + nb * 32;
#pragma unroll
            for (int u = 0; u < 4; u++) ((uint4*)dst)[u] = srow[u];
        }
        if (tt == 2) {
            // vout fp32 [t,b,h,n,hd]
            int t = tid >> 6, rem = tid & 63;
            int hl = rem >> 5, n = rem & 31;
            int h = msub * 2 + hl;
            float* dst = vout + ((((size_t)(t * 32 + b) * NH + h) * HW_) + nb * 32 + n) * HD;
#pragma unroll
            for (int c4 = 0; c4 < 16; c4++) {
                float4 f;
                f.x = __half2float(sm[hl * 64 + c4 * 4 + 0][t * 32 + n]);
                f.y = __half2float(sm[hl * 64 + c4 * 4 + 1][t * 32 + n]);
                f.z = __half2float(sm[hl * 64 + c4 * 4 + 2][t * 32 + n]);
                f.w = __half2float(sm[hl * 64 + c4 * 4 + 3][t * 32 + n]);
                ((float4*)dst)[c4] = f;
            }
        }
    } else {
        // ---- proj epilogue ----
#pragma unroll
        for (int i = 0; i < 4; i++) {
            int mloc = m0 + wm * 64 + i * 16 + g;
#pragma unroll
            for (int half = 0; half < 2; half++) {
                int c = mloc + half * 8;
                float sc = scale[c], bi = bias[c], cb = cbias[c];
                float* dst = outp + (size_t)bz * CN + (size_t)c * HW_;
                const float* idp = identity + (size_t)bz * CN + (size_t)c * HW_;
#pragma unroll
                for (int jj = 0; jj < 4; jj++) {
                    int col = n0 + wn * 32 + jj * 8 + 2 * tg;
                    float2 id2 = *(const float2*)&idp[col];
                    float2 v2;
                    v2.x = (acc[i][jj][half * 2 + 0] + cb) * sc + bi + id2.x;
                    v2.y = (acc[i][jj][half * 2 + 1] + cb) * sc + bi + id2.y;
                    *(float2*)&dst[col] = v2;
                }
            }
        }
    }
}

// ---------------------------------------------------------------------------
// attn HMMA: attnT[chunk,b,h][de][dh] = (1/16) * sum_{t in chunk, s} v[de,s]*k[dh,s]
// ---------------------------------------------------------------------------
__global__ void __launch_bounds__(128) attn_hmma_kernel(
    const __half* __restrict__ ksp, const __half* __restrict__ vsp,
    __half* __restrict__ attnT)
{
    __shared__ __half sv[64][72];
    __shared__ __half sk[64][72];
    uint32_t sv_u = smem_to_u32(&sv[0][0]);
    uint32_t sk_u = smem_to_u32(&sk[0][0]);

    int cbh = blockIdx.x;
    int h = cbh & 7, b = (cbh >> 3) & 31, chunk = cbh >> 8;
    int tid = threadIdx.x;
    int wid = tid >> 5, lane = tid & 31;

    float acc[8][4];
#pragma unroll
    for (int j = 0; j < 8; j++)
#pragma unroll
        for (int e = 0; e < 4; e++) acc[j][e] = 0.f;

    for (int st = 0; st < 8; st++) {
        int t = chunk * 2 + (st >> 2);
        int n0 = (st & 3) * 64;
        size_t base = (size_t)t * SLICE + ((size_t)(b * C_ + h * HD)) * HW_ + n0;
#pragma unroll
        for (int l = 0; l < 4; l++) {
            int lin = l * 128 + tid;
            int r = lin >> 3, sg = lin & 7;
            *(uint4*)((char*)sv + r * 144 + sg * 16) =
                *(const uint4*)(vsp + base + (size_t)r * HW_ + sg * 8);
            *(uint4*)((char*)sk + r * 144 + sg * 16) =
                *(const uint4*)(ksp + base + (size_t)r * HW_ + sg * 8);
        }
        __syncthreads();

#pragma unroll
        for (int kk = 0; kk < 4; kk++) {
            uint32_t a[4];
            {
                uint32_t row = wid * 16 + (lane & 15);
                uint32_t col = kk * 16 + ((lane >> 4) << 3);
                ldsm4(a, sv_u + (row * 72 + col) * 2);
            }
            uint32_t bf[4][4];
#pragma unroll
            for (int j2 = 0; j2 < 4; j2++) {
                uint32_t row = j2 * 16 + (lane & 7) + ((lane >> 4) << 3);
                uint32_t col = kk * 16 + (((lane >> 3) & 1) << 3);
                ldsm4(bf[j2], sk_u + (row * 72 + col) * 2);
            }
#pragma unroll
            for (int j = 0; j < 8; j++)
                mma16816h(acc[j], a, bf[j >> 1][(j & 1) * 2], bf[j >> 1][(j & 1) * 2 + 1]);
        }
        __syncthreads();
    }

    __half* ap = attnT + ((size_t)((chunk * B_ + b) * NH + h)) * (HD * HD);
    int g = lane >> 2, tg = lane & 3;
#pragma unroll
    for (int j = 0; j < 8; j++)
#pragma unroll
        for (int e = 0; e < 2; e++) {
            int row = wid * 16 + g + e * 8;       // de
            int col = j * 8 + tg * 2;             // dh
            __half2 h2 = __floats2half2_rn(acc[j][e * 2] * 0.0625f,
                                           acc[j][e * 2 + 1] * 0.0625f);
            *(__half2*)(ap + (size_t)row * HD + col) = h2;
        }
}

// ---------------------------------------------------------------------------
// x2 HMMA + LIF(0.5): out[de][n] = sum_dh attnT[de][dh] * q[dh][n]
//   q consumed in [c][n] layout via ldmatrix.trans (no qT transpose needed).
//   Output staged in smem, written coalesced to x2T [tb][n][c].
// grid (2 nhalf, 8 h, 32 b), 256 threads (8 warps: wm=de quarter, wn=n half)
// ---------------------------------------------------------------------------
#define SQN 136   // sq row stride in halves (272B, 17x16B -> conflict-free ldsm)

__global__ void __launch_bounds__(256) x2_hmma_kernel(
    const __half* __restrict__ qsp, const __half* __restrict__ attnT,
    __half* __restrict__ x2T)
{
    __shared__ __half sq[64][SQN];    // [dh][n]  (q spikes, K-rows)
    __shared__ __half sa[64][72];     // [de][dh] (attnT)
    __shared__ __half sx[128][72];    // [n][de] staging for coalesced output
    uint32_t sq_u = smem_to_u32(&sq[0][0]);
    uint32_t sa_u = smem_to_u32(&sa[0][0]);

    int nhalf = blockIdx.x, h = blockIdx.y, b = blockIdx.z;
    int tid = threadIdx.x;
    int wid = tid >> 5, lane = tid & 31;
    int wm = wid >> 1, wn = wid & 1;
    int g = lane >> 2, tg = lane & 3;

    float mem[8][4];
#pragma unroll
    for (int j = 0; j < 8; j++)
#pragma unroll
        for (int e = 0; e < 4; e++) mem[j][e] = 0.f;

#pragma unroll
    for (int t = 0; t < T_; t++) {
        if ((t & 1) == 0) {
            int chunk = t >> 1;
            const __half* ap = attnT + ((size_t)((chunk * B_ + b) * NH + h)) * (HD * HD);
#pragma unroll
            for (int l = 0; l < 2; l++) {
                int lin = l * 256 + tid;
                int r = lin >> 3, sg = lin & 7;
                *(uint4*)((char*)sa + r * 144 + sg * 16) =
                    *(const uint4*)(ap + (size_t)r * HD + sg * 8);
            }
        }
        {
            // q [c][n]: 64 rows (dh), 128 n-cols for this nhalf
            const __half* qp = qsp + (size_t)t * SLICE
                             + ((size_t)(b * C_ + h * HD)) * HW_ + nhalf * 128;
#pragma unroll
            for (int l = 0; l < 4; l++) {
                int lin = l * 256 + tid;
                int r = lin >> 4, sg = lin & 15;
                *(uint4*)((char*)sq + r * (SQN * 2) + sg * 16) =
                    *(const uint4*)(qp + (size_t)r * HW_ + sg * 8);
            }
        }
        __syncthreads();

        float acc[8][4];
#pragma unroll
        for (int j = 0; j < 8; j++)
#pragma unroll
            for (int e = 0; e < 4; e++) acc[j][e] = 0.f;

#pragma unroll
        for (int kk = 0; kk < 4; kk++) {
            uint32_t a[4];
            {
                uint32_t row = wm * 16 + (lane & 15);
                uint32_t col = kk * 16 + ((lane >> 4) << 3);
                ldsm4(a, sa_u + (row * 72 + col) * 2);
            }
            uint32_t bf[4][4];
#pragma unroll
            for (int j2 = 0; j2 < 4; j2++) {
                // trans-ldmatrix on [k][n] storage -> same fragment as
                // non-trans on [n][k]:
                //   r0=(n0-7,k0-7) r1=(n0-7,k8-15) r2=(n8-15,k0-7) r3=(n8-15,k8-15)
                uint32_t krow = kk * 16 + (((lane >> 3) & 1) << 3) + (lane & 7);
                uint32_t ncol = wn * 64 + j2 * 16 + ((lane >> 4) << 3);
                ldsm4t(bf[j2], sq_u + (krow * SQN + ncol) * 2);
            }
#pragma unroll
            for (int j = 0; j < 8; j++)
                mma16816h(acc[j], a, bf[j >> 1][(j & 1) * 2], bf[j >> 1][(j & 1) * 2 + 1]);
        }

        // LIF (vth = 0.5) -> stage spikes into sx[n][de]
#pragma unroll
        for (int j = 0; j < 8; j++)
#pragma unroll
            for (int e = 0; e < 4; e++) {
                float xv = acc[j][e];
                mem[j][e] = mem[j][e] + (xv - mem[j][e]) * 0.5f;
                float s = (mem[j][e] >= 0.5f) ? 1.0f : 0.0f;
                if (s != 0.f) mem[j][e] = 0.f;
                int n = wn * 64 + j * 8 + tg * 2 + (e & 1);
                int de = wm * 16 + g + ((e >> 1) << 3);
                sx[n][de] = __float2half(s);
            }
        __syncthreads();

        // coalesced write: x2T[(t*B+b)*HW + nhalf*128 + n][h*64 .. +63]
        {
            __half* obase = x2T + ((size_t)(t * B_ + b) * HW_ + nhalf * 128) * C_ + h * HD;
#pragma unroll
            for (int l = 0; l < 2; l++) {
                int idx = l * 256 + tid;        // 0..511
                int n = idx >> 2, seg = idx & 3;
                *(uint4*)(obase + (size_t)n * C_ + seg * 16) =
                    *(const uint4*)(&sx[n][seg * 16]);
            }
        }
        __syncthreads();
    }
}

// ---------------------------------------------------------------------------
extern "C" void kernel_launch(void* const* d_in, const int* in_sizes, int n_in,
                              void* d_out, int out_size)
{
    const float* x       = (const float*)d_in[0];
    const float* Wq      = (const float*)d_in[1];
    const float* q_scale = (const float*)d_in[2];
    const float* q_bias  = (const float*)d_in[3];
    const float* Wk      = (const float*)d_in[4];
    const float* k_scale = (const float*)d_in[5];
    const float* k_bias  = (const float*)d_in[6];
    const float* Wv      = (const float*)d_in[7];
    const float* v_scale = (const float*)d_in[8];
    const float* v_bias  = (const float*)d_in[9];
    const float* Wp      = (const float*)d_in[10];
    const float* bp      = (const float*)d_in[11];
    const float* p_scale = (const float*)d_in[12];
    const float* p_bias  = (const float*)d_in[13];
    float* out = (float*)d_out;

    __half *xsB, *qsp, *ksp, *vsp, *x2T, *attnT, *wsplit;
    float *gscale, *gbias;
    cudaGetSymbolAddress((void**)&xsB,    g_xsB);
    cudaGetSymbolAddress((void**)&qsp,    g_qs);
    cudaGetSymbolAddress((void**)&ksp,    g_ks);
    cudaGetSymbolAddress((void**)&vsp,    g_vs);
    cudaGetSymbolAddress((void**)&x2T,    g_x2T);
    cudaGetSymbolAddress((void**)&attnT,  g_attnT);
    cudaGetSymbolAddress((void**)&wsplit, g_wsplit);
    cudaGetSymbolAddress((void**)&gscale, g_scale);
    cudaGetSymbolAddress((void**)&gbias,  g_bias);

    const int SMEM_BYTES = 2 * STAGE_BYTES;   // 73728
    cudaFuncSetAttribute(gemm_hmma_kernel<0>, cudaFuncAttributeMaxDynamicSharedMemorySize, SMEM_BYTES);
    cudaFuncSetAttribute(gemm_hmma_kernel<1>, cudaFuncAttributeMaxDynamicSharedMemorySize, SMEM_BYTES);

    // 0. weight splits (fp16 hi/mid', exact) + scale/bias concat
    wsplit_kernel<<<4096, 256>>>(Wq, Wk, Wv, Wp, wsplit);
    sb_kernel<<<6, 256>>>(q_scale, q_bias, k_scale, k_bias, v_scale, v_bias, gscale, gbias);

    // 1. shortcut LIF + transpose -> xsB [b][n'][c] (t folded into n')
    lif_in_trans_kernel<<<dim3(4, 8, 32), 256>>>(x, xsB);

    // 2. q/k/v conv + BN + LIF fused in GEMM epilogue -> q/k/v [t,b,c,n] + vout
    gemm_hmma_kernel<0><<<dim3(8, 12, 32), 256, SMEM_BYTES>>>(
        wsplit, xsB, qsp, ksp, vsp, out + TOTAL,
        gscale, gbias, nullptr, nullptr, nullptr, 0);

    // 3. attnT = (1/16) (k^T v)^T per (chunk, b, h), HMMA fp16 (exact)
    attn_hmma_kernel<<<2 * B_ * NH, 128>>>(ksp, vsp, attnT);

    // 4. x2 = attn^T @ q + LIF(0.5), HMMA fp16 (q via ldsm.trans), -> x2T [tb][n][c]
    x2_hmma_kernel<<<dim3(2, NH, B_), 256>>>(qsp, attnT, x2T);

    // 5. proj conv (hi split) + BN + identity via HMMA -> out[0 : TOTAL)
    gemm_hmma_kernel<1><<<dim3(2, 4, 128), 256, SMEM_BYTES>>>(
        wsplit, x2T, nullptr, nullptr, nullptr, nullptr,
        p_scale, p_bias, bp, x, out, 1536);
}

// round 12
// speedup vs baseline: 1.5525x; 1.0311x over previous
#include <cuda_runtime.h>
#include <cuda_fp16.h>
#include <cstdint>

// Problem constants
#define T_    4
#define B_    32
#define C_    512
#define HW_   256
#define NH    8
#define HD    64
#define SLICE 4194304      // B*C*HW = one time slice
#define TOTAL 16777216     // T*B*C*HW
#define CN    131072       // C*HW per (t,b)

// ---------------------------------------------------------------------------
// helpers
// ---------------------------------------------------------------------------
__device__ __forceinline__ uint32_t smem_to_u32(const void* smem_ptr) {
    uint32_t addr;
    asm("{ .reg .u64 tmp; cvta.to.shared.u64 tmp, %1; cvt.u32.u64 %0, tmp; }"
        : "=r"(addr) : "l"(smem_ptr));
    return addr;
}

__device__ __forceinline__ void cp16(uint32_t dst, const void* src) {
    asm volatile("cp.async.ca.shared.global [%0], [%1], 16;" :: "r"(dst), "l"(src));
}

__device__ __forceinline__ void ldsm4(uint32_t* r, uint32_t addr) {
    asm volatile("ldmatrix.sync.aligned.m8n8.x4.shared.b16 {%0,%1,%2,%3}, [%4];"
                 : "=r"(r[0]), "=r"(r[1]), "=r"(r[2]), "=r"(r[3]) : "r"(addr));
}

__device__ __forceinline__ void ldsm4t(uint32_t* r, uint32_t addr) {
    asm volatile("ldmatrix.sync.aligned.m8n8.x4.trans.shared.b16 {%0,%1,%2,%3}, [%4];"
                 : "=r"(r[0]), "=r"(r[1]), "=r"(r[2]), "=r"(r[3]) : "r"(addr));
}

__device__ __forceinline__ void mma16816h(float* c, const uint32_t* a,
                                          uint32_t b0, uint32_t b1) {
    asm volatile(
        "mma.sync.aligned.m16n8k16.row.col.f32.f16.f16.f32 "
        "{%0,%1,%2,%3}, {%4,%5,%6,%7}, {%8,%9}, {%0,%1,%2,%3};"
        : "+f"(c[0]), "+f"(c[1]), "+f"(c[2]), "+f"(c[3])
        : "r"(a[0]), "r"(a[1]), "r"(a[2]), "r"(a[3]), "r"(b0), "r"(b1));
}

// ---------------------------------------------------------------------------
// Scratch (static device globals)
// ---------------------------------------------------------------------------
__device__ __half g_xsB[TOTAL];              // x spikes, per-b matrix [b][n'][c]
__device__ __half g_qs[TOTAL];               // q spikes, [t,b,c,n] fp16
__device__ __half g_ks[TOTAL];               // k spikes, [t,b,c,n] fp16
__device__ __half g_vs[TOTAL];               // v spikes, [t,b,c,n] fp16
__device__ __half g_x2T[TOTAL];              // x2 spikes, [tb][n][c] fp16
__device__ __half g_wsplit[2u * 2048u * 512u];      // [split: 0=mid',1=hi][2048][512]
__device__ float  g_scale[3 * C_];
__device__ float  g_bias [3 * C_];

// ---------------------------------------------------------------------------
// Prep: exact 2-way fp16 split of the 4 weight matrices + scale/bias concat
// ---------------------------------------------------------------------------
__global__ void wsplit_kernel(const float* __restrict__ Wq, const float* __restrict__ Wk,
                              const float* __restrict__ Wv, const float* __restrict__ Wp,
                              __half* __restrict__ ws,
                              const float* __restrict__ qs, const float* __restrict__ qb,
                              const float* __restrict__ ks, const float* __restrict__ kb,
                              const float* __restrict__ vs, const float* __restrict__ vb,
                              float* __restrict__ gs, float* __restrict__ gb)
{
    int i = blockIdx.x * 256 + threadIdx.x;      // 0 .. 2048*512-1
    int r = i >> 9;
    int kk = i & 511;
    const float* W = (r < 512) ? Wq : (r < 1024) ? Wk : (r < 1536) ? Wv : Wp;
    float w = W[(size_t)(r & 511) * 512 + kk];
    __half hi = __float2half_rn(w);
    float r1 = w - __half2float(hi);
    __half mid = __float2half_rn(r1 * 4096.0f);
    ws[i]            = mid;
    ws[1048576u + i] = hi;

    // fold sb concat into the first 6 blocks
    if (i < 1536) {
        if (i < 512)       { gs[i] = qs[i];        gb[i] = qb[i]; }
        else if (i < 1024) { gs[i] = ks[i - 512];  gb[i] = kb[i - 512]; }
        else               { gs[i] = vs[i - 1024]; gb[i] = vb[i - 1024]; }
    }
}

// ---------------------------------------------------------------------------
// K1: shortcut LIF on x fused with transpose -> xsB fp16 [b][n'][c]
//   n' = (n>>3)*32 + t*8 + (n&7)
// ---------------------------------------------------------------------------
__global__ void lif_in_trans_kernel(const float* __restrict__ x,
                                    __half* __restrict__ xsB)
{
    __shared__ __half tile[64][65];
    int nblk = blockIdx.x, cblk = blockIdx.y, b = blockIdx.z;
    int tid = threadIdx.x;

    float v[16];
#pragma unroll
    for (int p = 0; p < 16; p++) v[p] = 0.f;

    __half* D = xsB + (size_t)b * (1024 * 512);

#pragma unroll
    for (int t = 0; t < T_; t++) {
        if (t) __syncthreads();
#pragma unroll
        for (int p = 0; p < 16; p++) {
            int c_l = p * 4 + (tid >> 6), n_l = tid & 63;
            float xv = x[(size_t)t * SLICE +
                         ((size_t)(b * C_ + cblk * 64 + c_l)) * HW_ + nblk * 64 + n_l];
            v[p] = v[p] + (xv - v[p]) * 0.5f;
            float s = (v[p] >= 1.0f) ? 1.0f : 0.0f;
            if (s != 0.f) v[p] = 0.f;
            tile[c_l][n_l] = __float2half(s);
        }
        __syncthreads();
#pragma unroll
        for (int p = 0; p < 16; p++) {
            int c_l = tid & 63, n_l = p * 4 + (tid >> 6);
            int n = nblk * 64 + n_l;
            int nprime = (n >> 3) * 32 + t * 8 + (n & 7);
            D[(size_t)nprime * C_ + cblk * 64 + c_l] = tile[c_l][n_l];
        }
    }
}

// ---------------------------------------------------------------------------
// HMMA GEMM: CTA 128x128, 2x4 warps of 64x32, TWO-stage double buffer
// MODE 0: qkv, 16 stages (8 mid' + 8 hi, exact). Epilogue: BN -> LIF(vth=1)
//         -> q/k/v all in [t,b,c,n] (+ vout fp32). grid (8 nblk, 12 mtile, 32 b)
// MODE 1: proj, hi-split ONLY (8 stages). grid (2 ntile, 4 mtile, 128 tb)
// ---------------------------------------------------------------------------
#define STAGE_BYTES 36864
#define A_BYTES     18432
#define SM_STRIDE   136          // halves; 272B row stride

template<int MODE>
__global__ void __launch_bounds__(256, 2) gemm_hmma_kernel(
    const __half* __restrict__ wsplit,            // [2][2048][512]
    const __half* __restrict__ Bmat,              // MODE0: xsB ; MODE1: x2T
    __half* __restrict__ qsp, __half* __restrict__ ksp, __half* __restrict__ vsp,
    float* __restrict__ vout,
    const float* __restrict__ scale, const float* __restrict__ bias,
    const float* __restrict__ cbias, const float* __restrict__ identity,
    float* __restrict__ outp, int wrow_base)
{
    constexpr int NS = (MODE == 0) ? 16 : 8;
    extern __shared__ __align__(128) char smem[];
    uint32_t smem_u = smem_to_u32(smem);
    const int tid = threadIdx.x;
    const int wid = tid >> 5, lane = tid & 31;
    const int wm = wid >> 2, wn = wid & 3;         // 2 x 4 warp grid, 64x32 tiles
    const int n0 = blockIdx.x * 128;
    const int m0 = blockIdx.y * 128;
    const int bz = blockIdx.z;
    const char* Bbase = (MODE == 0)
        ? (const char*)(Bmat + (size_t)bz * (1024 * 512))
        : (const char*)(Bmat + (size_t)bz * CN);

    float acc[4][4][4];
#pragma unroll
    for (int i = 0; i < 4; i++)
#pragma unroll
        for (int j = 0; j < 4; j++)
#pragma unroll
            for (int e = 0; e < 4; e++) acc[i][j][e] = 0.f;

    auto cp_stage = [&](int s) {
        int buf = s & 1;
        int split = (MODE == 0) ? (s >> 3) : 1;   // MODE1: hi only
        int kA = (s & 7) << 6;
        const char* Ag = (const char*)wsplit
                       + ((size_t)split * 2048 + (size_t)(wrow_base + m0)) * 1024
                       + (size_t)kA * 2;
        const char* Bg = Bbase + (size_t)n0 * 1024 + (size_t)kA * 2;
        uint32_t sA = smem_u + buf * STAGE_BYTES;
        uint32_t sB = sA + A_BYTES;
#pragma unroll
        for (int p = 0; p < 4; p++) {
            int lin = p * 256 + tid;
            int r = lin >> 3, sg = lin & 7;
            cp16(sA + r * 144 + sg * 16, Ag + (size_t)r * 1024 + sg * 16);
            cp16(sB + r * 144 + sg * 16, Bg + (size_t)r * 1024 + sg * 16);
        }
        asm volatile("cp.async.commit_group;");
    };

    cp_stage(0);

    for (int s = 0; s < NS; s++) {
        if (s + 1 < NS) {
            cp_stage(s + 1);
            asm volatile("cp.async.wait_group 1;");
        } else {
            asm volatile("cp.async.wait_group 0;");
        }
        __syncthreads();

        uint32_t sA = smem_u + (s & 1) * STAGE_BYTES;
        uint32_t sB = sA + A_BYTES;

#pragma unroll
        for (int kk = 0; kk < 4; kk++) {
            uint32_t a[4][4];
#pragma unroll
            for (int i = 0; i < 4; i++) {
                uint32_t row = wm * 64 + i * 16 + (lane & 15);
                uint32_t col = kk * 16 + ((lane >> 4) << 3);
                ldsm4(a[i], sA + (row * 72 + col) * 2);
            }
            uint32_t bf[2][4];
#pragma unroll
            for (int j2 = 0; j2 < 2; j2++) {
                uint32_t row = wn * 32 + j2 * 16 + (lane & 7) + ((lane >> 4) << 3);
                uint32_t col = kk * 16 + (((lane >> 3) & 1) << 3);
                ldsm4(bf[j2], sB + (row * 72 + col) * 2);
            }
#pragma unroll
            for (int i = 0; i < 4; i++)
#pragma unroll
                for (int jj = 0; jj < 4; jj++) {
                    uint32_t b0 = bf[jj >> 1][(jj & 1) * 2 + 0];
                    uint32_t b1 = bf[jj >> 1][(jj & 1) * 2 + 1];
                    mma16816h(acc[i][jj], a[i], b0, b1);
                }
        }
        if (MODE == 0 && s == 7) {
#pragma unroll
            for (int i = 0; i < 4; i++)
#pragma unroll
                for (int j = 0; j < 4; j++)
#pragma unroll
                    for (int e = 0; e < 4; e++) acc[i][j][e] *= 0.000244140625f;
        }
        __syncthreads();
    }

    int g = lane >> 2, tg = lane & 3;

    if (MODE == 0) {
        // ---- BN + LIF (vth=1) in registers: jj == t ----
        __half (*sm)[SM_STRIDE] = (__half(*)[SM_STRIDE])smem;
#pragma unroll
        for (int i = 0; i < 4; i++) {
#pragma unroll
            for (int eh = 0; eh < 2; eh++) {
                int rl = wm * 64 + i * 16 + g + eh * 8;
                float sc = scale[m0 + rl], bi = bias[m0 + rl];
#pragma unroll
                for (int e1 = 0; e1 < 2; e1++) {
                    int nl = wn * 8 + 2 * tg + e1;        // n_local 0..31
                    float v = 0.f;
#pragma unroll
                    for (int t = 0; t < T_; t++) {
                        float xv = acc[i][t][eh * 2 + e1] * sc + bi;
                        v = v + (xv - v) * 0.5f;
                        float ss = (v >= 1.0f) ? 1.0f : 0.0f;
                        if (ss != 0.f) v = 0.f;
                        sm[rl][t * 32 + nl] = __float2half(ss);
                    }
                }
            }
        }
        __syncthreads();

        int tt   = blockIdx.y >> 2;      // 0 q, 1 k, 2 v
        int msub = blockIdx.y & 3;       // 128-row block within tensor
        int b    = bz;
        int nb   = blockIdx.x;           // n base = nb*32

        __half* base = (tt == 0) ? qsp : (tt == 1) ? ksp : vsp;
#pragma unroll
        for (int p = 0; p < 2; p++) {
            int rid = p * 256 + tid;       // 0..511
            int t = rid >> 7, cl = rid & 127;
            const uint4* srow = (const uint4*)&sm[cl][t * 32];
            __half* dst = base + (size_t)t * SLICE
                        + ((size_t)(b * C_ + msub * 128 + cl)) * HW_ + nb * 32;
#pragma unroll
            for (int u = 0; u < 4; u++) ((uint4*)dst)[u] = srow[u];
        }
        if (tt == 2) {
            // vout fp32 [t,b,h,n,hd]
            int t = tid >> 6, rem = tid & 63;
            int hl = rem >> 5, n = rem & 31;
            int h = msub * 2 + hl;
            float* dst = vout + ((((size_t)(t * 32 + b) * NH + h) * HW_) + nb * 32 + n) * HD;
#pragma unroll
            for (int c4 = 0; c4 < 16; c4++) {
                float4 f;
                f.x = __half2float(sm[hl * 64 + c4 * 4 + 0][t * 32 + n]);
                f.y = __half2float(sm[hl * 64 + c4 * 4 + 1][t * 32 + n]);
                f.z = __half2float(sm[hl * 64 + c4 * 4 + 2][t * 32 + n]);
                f.w = __half2float(sm[hl * 64 + c4 * 4 + 3][t * 32 + n]);
                ((float4*)dst)[c4] = f;
            }
        }
    } else {
        // ---- proj epilogue ----
#pragma unroll
        for (int i = 0; i < 4; i++) {
            int mloc = m0 + wm * 64 + i * 16 + g;
#pragma unroll
            for (int half = 0; half < 2; half++) {
                int c = mloc + half * 8;
                float sc = scale[c], bi = bias[c], cb = cbias[c];
                float* dst = outp + (size_t)bz * CN + (size_t)c * HW_;
                const float* idp = identity + (size_t)bz * CN + (size_t)c * HW_;
#pragma unroll
                for (int jj = 0; jj < 4; jj++) {
                    int col = n0 + wn * 32 + jj * 8 + 2 * tg;
                    float2 id2 = *(const float2*)&idp[col];
                    float2 v2;
                    v2.x = (acc[i][jj][half * 2 + 0] + cb) * sc + bi + id2.x;
                    v2.y = (acc[i][jj][half * 2 + 1] + cb) * sc + bi + id2.y;
                    *(float2*)&dst[col] = v2;
                }
            }
        }
    }
}

// ---------------------------------------------------------------------------
// FUSED attn + x2 kernel, one CTA per (h, b), 256 threads.
// Phase A: warps 0-3 compute attnT for chunk 0, warps 4-7 for chunk 1
//          (identical math/order to the old attn kernel); result -> smem fp16.
// Phase B: x2 = attnT @ q (q via ldsm.trans) + LIF(0.5) -> x2T [tb][n][c].
// Dynamic smem layout (bytes):
//   sv/sk per group: group*18432 + {0, 9216}
//   attnT:  36864 + chunk*9216   (row stride 144B)
//   sq:     55296  (64 rows x 272B)
//   sx:     73728  (128 x 144B)
// ---------------------------------------------------------------------------
#define FA_AT    36864
#define FA_SQ    55296
#define FA_SX    73728
#define FA_TOTAL 92160
#define SQN      136

__global__ void __launch_bounds__(256) attn_x2_kernel(
    const __half* __restrict__ ksp, const __half* __restrict__ vsp,
    const __half* __restrict__ qsp, __half* __restrict__ x2T)
{
    extern __shared__ __align__(128) char fsm[];
    uint32_t smem_u = smem_to_u32(fsm);
    int h = blockIdx.x, b = blockIdx.y;
    int tid = threadIdx.x;
    int wid = tid >> 5, lane = tid & 31;
    int g = lane >> 2, tg = lane & 3;

    // ---------------- Phase A: attn ----------------
    {
        int group = tid >> 7;         // == chunk
        int gtid = tid & 127;
        int gwid = gtid >> 5;
        uint32_t sv_u = smem_u + group * 18432;
        uint32_t sk_u = sv_u + 9216;

        float acc[8][4];
#pragma unroll
        for (int j = 0; j < 8; j++)
#pragma unroll
            for (int e = 0; e < 4; e++) acc[j][e] = 0.f;

        for (int st = 0; st < 8; st++) {
            int t = group * 2 + (st >> 2);
            int n0 = (st & 3) * 64;
            size_t base = (size_t)t * SLICE + ((size_t)(b * C_ + h * HD)) * HW_ + n0;
#pragma unroll
            for (int l = 0; l < 4; l++) {
                int lin = l * 128 + gtid;
                int r = lin >> 3, sg = lin & 7;
                *(uint4*)(fsm + (sv_u - smem_u) + r * 144 + sg * 16) =
                    *(const uint4*)(vsp + base + (size_t)r * HW_ + sg * 8);
                *(uint4*)(fsm + (sk_u - smem_u) + r * 144 + sg * 16) =
                    *(const uint4*)(ksp + base + (size_t)r * HW_ + sg * 8);
            }
            __syncthreads();

#pragma unroll
            for (int kk = 0; kk < 4; kk++) {
                uint32_t a[4];
                {
                    uint32_t row = gwid * 16 + (lane & 15);
                    uint32_t col = kk * 16 + ((lane >> 4) << 3);
                    ldsm4(a, sv_u + (row * 72 + col) * 2);
                }
                uint32_t bf[4][4];
#pragma unroll
                for (int j2 = 0; j2 < 4; j2++) {
                    uint32_t row = j2 * 16 + (lane & 7) + ((lane >> 4) << 3);
                    uint32_t col = kk * 16 + (((lane >> 3) & 1) << 3);
                    ldsm4(bf[j2], sk_u + (row * 72 + col) * 2);
                }
#pragma unroll
                for (int j = 0; j < 8; j++)
                    mma16816h(acc[j], a, bf[j >> 1][(j & 1) * 2], bf[j >> 1][(j & 1) * 2 + 1]);
            }
            __syncthreads();
        }

        // store attnT (values = count/16, exact) to smem, row stride 72 halves
        uint32_t at_u = smem_u + FA_AT + group * 9216;
#pragma unroll
        for (int j = 0; j < 8; j++)
#pragma unroll
            for (int e = 0; e < 2; e++) {
                int row = gwid * 16 + g + e * 8;       // de
                int col = j * 8 + tg * 2;              // dh
                __half2 h2 = __floats2half2_rn(acc[j][e * 2] * 0.0625f,
                                               acc[j][e * 2 + 1] * 0.0625f);
                *(__half2*)(fsm + (at_u - smem_u) + (row * 72 + col) * 2) = h2;
            }
    }
    __syncthreads();

    // ---------------- Phase B: x2 ----------------
    int wm = wid >> 1, wn = wid & 1;
    uint32_t sq_u = smem_u + FA_SQ;
    __half (*sx)[72] = (__half(*)[72])(fsm + FA_SX);

    for (int nhalf = 0; nhalf < 2; nhalf++) {
        float mem[8][4];
#pragma unroll
        for (int j = 0; j < 8; j++)
#pragma unroll
            for (int e = 0; e < 4; e++) mem[j][e] = 0.f;

#pragma unroll
        for (int t = 0; t < T_; t++) {
            uint32_t sa_u = smem_u + FA_AT + (t >> 1) * 9216;
            {
                const __half* qp = qsp + (size_t)t * SLICE
                                 + ((size_t)(b * C_ + h * HD)) * HW_ + nhalf * 128;
#pragma unroll
                for (int l = 0; l < 4; l++) {
                    int lin = l * 256 + tid;
                    int r = lin >> 4, sg = lin & 15;
                    *(uint4*)(fsm + FA_SQ + r * (SQN * 2) + sg * 16) =
                        *(const uint4*)(qp + (size_t)r * HW_ + sg * 8);
                }
            }
            __syncthreads();

            float acc[8][4];
#pragma unroll
            for (int j = 0; j < 8; j++)
#pragma unroll
                for (int e = 0; e < 4; e++) acc[j][e] = 0.f;

#pragma unroll
            for (int kk = 0; kk < 4; kk++) {
                uint32_t a[4];
                {
                    uint32_t row = wm * 16 + (lane & 15);
                    uint32_t col = kk * 16 + ((lane >> 4) << 3);
                    ldsm4(a, sa_u + (row * 72 + col) * 2);
                }
                uint32_t bf[4][4];
#pragma unroll
                for (int j2 = 0; j2 < 4; j2++) {
                    uint32_t krow = kk * 16 + (((lane >> 3) & 1) << 3) + (lane & 7);
                    uint32_t ncol = wn * 64 + j2 * 16 + ((lane >> 4) << 3);
                    ldsm4t(bf[j2], sq_u + (krow * SQN + ncol) * 2);
                }
#pragma unroll
                for (int j = 0; j < 8; j++)
                    mma16816h(acc[j], a, bf[j >> 1][(j & 1) * 2], bf[j >> 1][(j & 1) * 2 + 1]);
            }

            // LIF (vth = 0.5) -> stage spikes into sx[n][de]
#pragma unroll
            for (int j = 0; j < 8; j++)
#pragma unroll
                for (int e = 0; e < 4; e++) {
                    float xv = acc[j][e];
                    mem[j][e] = mem[j][e] + (xv - mem[j][e]) * 0.5f;
                    float s = (mem[j][e] >= 0.5f) ? 1.0f : 0.0f;
                    if (s != 0.f) mem[j][e] = 0.f;
                    int n = wn * 64 + j * 8 + tg * 2 + (e & 1);
                    int de = wm * 16 + g + ((e >> 1) << 3);
                    sx[n][de] = __float2half(s);
                }
            __syncthreads();

            // coalesced write: x2T[(t*B+b)*HW + nhalf*128 + n][h*64 .. +63]
            {
                __half* obase = x2T + ((size_t)(t * B_ + b) * HW_ + nhalf * 128) * C_ + h * HD;
#pragma unroll
                for (int l = 0; l < 2; l++) {
                    int idx = l * 256 + tid;        // 0..511
                    int n = idx >> 2, seg = idx & 3;
                    *(uint4*)(obase + (size_t)n * C_ + seg * 16) =
                        *(const uint4*)(&sx[n][seg * 16]);
                }
            }
            __syncthreads();
        }
    }
}

// ---------------------------------------------------------------------------
extern "C" void kernel_launch(void* const* d_in, const int* in_sizes, int n_in,
                              void* d_out, int out_size)
{
    const float* x       = (const float*)d_in[0];
    const float* Wq      = (const float*)d_in[1];
    const float* q_scale = (const float*)d_in[2];
    const float* q_bias  = (const float*)d_in[3];
    const float* Wk      = (const float*)d_in[4];
    const float* k_scale = (const float*)d_in[5];
    const float* k_bias  = (const float*)d_in[6];
    const float* Wv      = (const float*)d_in[7];
    const float* v_scale = (const float*)d_in[8];
    const float* v_bias  = (const float*)d_in[9];
    const float* Wp      = (const float*)d_in[10];
    const float* bp      = (const float*)d_in[11];
    const float* p_scale = (const float*)d_in[12];
    const float* p_bias  = (const float*)d_in[13];
    float* out = (float*)d_out;

    __half *xsB, *qsp, *ksp, *vsp, *x2T, *wsplit;
    float *gscale, *gbias;
    cudaGetSymbolAddress((void**)&xsB,    g_xsB);
    cudaGetSymbolAddress((void**)&qsp,    g_qs);
    cudaGetSymbolAddress((void**)&ksp,    g_ks);
    cudaGetSymbolAddress((void**)&vsp,    g_vs);
    cudaGetSymbolAddress((void**)&x2T,    g_x2T);
    cudaGetSymbolAddress((void**)&wsplit, g_wsplit);
    cudaGetSymbolAddress((void**)&gscale, g_scale);
    cudaGetSymbolAddress((void**)&gbias,  g_bias);

    const int SMEM_BYTES = 2 * STAGE_BYTES;   // 73728
    cudaFuncSetAttribute(gemm_hmma_kernel<0>, cudaFuncAttributeMaxDynamicSharedMemorySize, SMEM_BYTES);
    cudaFuncSetAttribute(gemm_hmma_kernel<1>, cudaFuncAttributeMaxDynamicSharedMemorySize, SMEM_BYTES);
    cudaFuncSetAttribute(attn_x2_kernel, cudaFuncAttributeMaxDynamicSharedMemorySize, FA_TOTAL);

    // 0. weight splits (fp16 hi/mid', exact) + scale/bias concat (fused)
    wsplit_kernel<<<4096, 256>>>(Wq, Wk, Wv, Wp, wsplit,
                                 q_scale, q_bias, k_scale, k_bias, v_scale, v_bias,
                                 gscale, gbias);

    // 1. shortcut LIF + transpose -> xsB [b][n'][c] (t folded into n')
    lif_in_trans_kernel<<<dim3(4, 8, 32), 256>>>(x, xsB);

    // 2. q/k/v conv + BN + LIF fused in GEMM epilogue -> q/k/v [t,b,c,n] + vout
    gemm_hmma_kernel<0><<<dim3(8, 12, 32), 256, SMEM_BYTES>>>(
        wsplit, xsB, qsp, ksp, vsp, out + TOTAL,
        gscale, gbias, nullptr, nullptr, nullptr, 0);

    // 3+4 fused: attn (smem) + x2 + LIF(0.5) -> x2T [tb][n][c]
    attn_x2_kernel<<<dim3(NH, B_), 256, FA_TOTAL>>>(ksp, vsp, qsp, x2T);

    // 5. proj conv (hi split) + BN + identity via HMMA -> out[0 : TOTAL)
    gemm_hmma_kernel<1><<<dim3(2, 4, 128), 256, SMEM_BYTES>>>(
        wsplit, x2T, nullptr, nullptr, nullptr, nullptr,
        p_scale, p_bias, bp, x, out, 1536);
}

// round 13
// speedup vs baseline: 1.6381x; 1.0552x over previous
#include <cuda_runtime.h>
#include <cuda_fp16.h>
#include <cstdint>

// Problem constants
#define T_    4
#define B_    32
#define C_    512
#define HW_   256
#define NH    8
#define HD    64
#define SLICE 4194304      // B*C*HW = one time slice
#define TOTAL 16777216     // T*B*C*HW
#define CN    131072       // C*HW per (t,b)

// ---------------------------------------------------------------------------
// helpers
// ---------------------------------------------------------------------------
__device__ __forceinline__ uint32_t smem_to_u32(const void* smem_ptr) {
    uint32_t addr;
    asm("{ .reg .u64 tmp; cvta.to.shared.u64 tmp, %1; cvt.u32.u64 %0, tmp; }"
        : "=r"(addr) : "l"(smem_ptr));
    return addr;
}

__device__ __forceinline__ void cp16(uint32_t dst, const void* src) {
    asm volatile("cp.async.ca.shared.global [%0], [%1], 16;" :: "r"(dst), "l"(src));
}

__device__ __forceinline__ void ldsm4(uint32_t* r, uint32_t addr) {
    asm volatile("ldmatrix.sync.aligned.m8n8.x4.shared.b16 {%0,%1,%2,%3}, [%4];"
                 : "=r"(r[0]), "=r"(r[1]), "=r"(r[2]), "=r"(r[3]) : "r"(addr));
}

__device__ __forceinline__ void ldsm4t(uint32_t* r, uint32_t addr) {
    asm volatile("ldmatrix.sync.aligned.m8n8.x4.trans.shared.b16 {%0,%1,%2,%3}, [%4];"
                 : "=r"(r[0]), "=r"(r[1]), "=r"(r[2]), "=r"(r[3]) : "r"(addr));
}

__device__ __forceinline__ void mma16816h(float* c, const uint32_t* a,
                                          uint32_t b0, uint32_t b1) {
    asm volatile(
        "mma.sync.aligned.m16n8k16.row.col.f32.f16.f16.f32 "
        "{%0,%1,%2,%3}, {%4,%5,%6,%7}, {%8,%9}, {%0,%1,%2,%3};"
        : "+f"(c[0]), "+f"(c[1]), "+f"(c[2]), "+f"(c[3])
        : "r"(a[0]), "r"(a[1]), "r"(a[2]), "r"(a[3]), "r"(b0), "r"(b1));
}

// ---------------------------------------------------------------------------
// Scratch (static device globals)
// ---------------------------------------------------------------------------
__device__ __half g_xsB[TOTAL];              // x spikes, per-b matrix [b][n'][c]
__device__ __half g_qs[TOTAL];               // q spikes, [t,b,c,n] fp16
__device__ __half g_ks[TOTAL];               // k spikes, [t,b,c,n] fp16
__device__ __half g_vs[TOTAL];               // v spikes, [t,b,c,n] fp16
__device__ __half g_x2T[TOTAL];              // x2 spikes, [tb][n][c] fp16
__device__ __half g_wsplit[2u * 2048u * 512u];      // [split: 0=mid',1=hi][2048][512]
__device__ float  g_scale[3 * C_];
__device__ float  g_bias [3 * C_];

// ---------------------------------------------------------------------------
// K1 (merged): blocks 0..1023  -> shortcut LIF + transpose (xsB [b][n'][c])
//              blocks 1024..2047 -> weight split (4 elems/thread) + sb concat
// ---------------------------------------------------------------------------
__global__ void prep_kernel(const float* __restrict__ x, __half* __restrict__ xsB,
                            const float* __restrict__ Wq, const float* __restrict__ Wk,
                            const float* __restrict__ Wv, const float* __restrict__ Wp,
                            __half* __restrict__ ws,
                            const float* __restrict__ qs, const float* __restrict__ qb,
                            const float* __restrict__ ks, const float* __restrict__ kb,
                            const float* __restrict__ vs, const float* __restrict__ vb,
                            float* __restrict__ gs, float* __restrict__ gb)
{
    __shared__ __half tile[64][65];
    int bid = blockIdx.x;
    int tid = threadIdx.x;

    if (bid >= 1024) {
        // ---- weight split: 4 consecutive k-elements per thread ----
        int base = (bid - 1024) * 1024 + tid * 4;     // 0 .. 2048*512-1, step 4
        int r = base >> 9;
        int kk = base & 511;
        const float* W = (r < 512) ? Wq : (r < 1024) ? Wk : (r < 1536) ? Wv : Wp;
        const float4 w4 = *(const float4*)&W[(size_t)(r & 511) * 512 + kk];
        const float wv[4] = {w4.x, w4.y, w4.z, w4.w};
        __half hi4[4], mid4[4];
#pragma unroll
        for (int u = 0; u < 4; u++) {
            __half hi = __float2half_rn(wv[u]);
            float r1 = wv[u] - __half2float(hi);
            hi4[u] = hi;
            mid4[u] = __float2half_rn(r1 * 4096.0f);
        }
        *(uint2*)&ws[base]             = *(uint2*)mid4;
        *(uint2*)&ws[1048576u + base]  = *(uint2*)hi4;

        // sb concat: first 2 blocks cover 1536 entries (3 per thread)
        int i = (bid - 1024) * 256 + tid;
        if (i < 512) {
            gs[i] = qs[i];               gb[i] = qb[i];
            gs[i + 512]  = ks[i];        gb[i + 512]  = kb[i];
            gs[i + 1024] = vs[i];        gb[i + 1024] = vb[i];
        }
        return;
    }

    // ---- LIF + transpose ----
    int nblk = bid & 3, cblk = (bid >> 2) & 7, b = bid >> 5;

    float v[16];
#pragma unroll
    for (int p = 0; p < 16; p++) v[p] = 0.f;

    __half* D = xsB + (size_t)b * (1024 * 512);

#pragma unroll
    for (int t = 0; t < T_; t++) {
        if (t) __syncthreads();
#pragma unroll
        for (int p = 0; p < 16; p++) {
            int c_l = p * 4 + (tid >> 6), n_l = tid & 63;
            float xv = x[(size_t)t * SLICE +
                         ((size_t)(b * C_ + cblk * 64 + c_l)) * HW_ + nblk * 64 + n_l];
            v[p] = v[p] + (xv - v[p]) * 0.5f;
            float s = (v[p] >= 1.0f) ? 1.0f : 0.0f;
            if (s != 0.f) v[p] = 0.f;
            tile[c_l][n_l] = __float2half(s);
        }
        __syncthreads();
#pragma unroll
        for (int p = 0; p < 16; p++) {
            int c_l = tid & 63, n_l = p * 4 + (tid >> 6);
            int n = nblk * 64 + n_l;
            int nprime = (n >> 3) * 32 + t * 8 + (n & 7);
            D[(size_t)nprime * C_ + cblk * 64 + c_l] = tile[c_l][n_l];
        }
    }
}

// ---------------------------------------------------------------------------
// HMMA GEMM: CTA 128x128, 2x4 warps of 64x32, TWO-stage double buffer
// MODE 0: qkv, 16 stages (8 mid' + 8 hi, exact). Epilogue: BN -> LIF(vth=1)
//         -> q/k/v all in [t,b,c,n] (+ vout fp32). grid (8 nblk, 12 mtile, 32 b)
// MODE 1: proj, hi-split ONLY (8 stages). grid (2 ntile, 4 mtile, 128 tb)
// ---------------------------------------------------------------------------
#define STAGE_BYTES 36864
#define A_BYTES     18432
#define SM_STRIDE   136          // halves; 272B row stride

template<int MODE>
__global__ void __launch_bounds__(256, 2) gemm_hmma_kernel(
    const __half* __restrict__ wsplit,            // [2][2048][512]
    const __half* __restrict__ Bmat,              // MODE0: xsB ; MODE1: x2T
    __half* __restrict__ qsp, __half* __restrict__ ksp, __half* __restrict__ vsp,
    float* __restrict__ vout,
    const float* __restrict__ scale, const float* __restrict__ bias,
    const float* __restrict__ cbias, const float* __restrict__ identity,
    float* __restrict__ outp, int wrow_base)
{
    constexpr int NS = (MODE == 0) ? 16 : 8;
    extern __shared__ __align__(128) char smem[];
    uint32_t smem_u = smem_to_u32(smem);
    const int tid = threadIdx.x;
    const int wid = tid >> 5, lane = tid & 31;
    const int wm = wid >> 2, wn = wid & 3;         // 2 x 4 warp grid, 64x32 tiles
    const int n0 = blockIdx.x * 128;
    const int m0 = blockIdx.y * 128;
    const int bz = blockIdx.z;
    const char* Bbase = (MODE == 0)
        ? (const char*)(Bmat + (size_t)bz * (1024 * 512))
        : (const char*)(Bmat + (size_t)bz * CN);

    float acc[4][4][4];
#pragma unroll
    for (int i = 0; i < 4; i++)
#pragma unroll
        for (int j = 0; j < 4; j++)
#pragma unroll
            for (int e = 0; e < 4; e++) acc[i][j][e] = 0.f;

    auto cp_stage = [&](int s) {
        int buf = s & 1;
        int split = (MODE == 0) ? (s >> 3) : 1;   // MODE1: hi only
        int kA = (s & 7) << 6;
        const char* Ag = (const char*)wsplit
                       + ((size_t)split * 2048 + (size_t)(wrow_base + m0)) * 1024
                       + (size_t)kA * 2;
        const char* Bg = Bbase + (size_t)n0 * 1024 + (size_t)kA * 2;
        uint32_t sA = smem_u + buf * STAGE_BYTES;
        uint32_t sB = sA + A_BYTES;
#pragma unroll
        for (int p = 0; p < 4; p++) {
            int lin = p * 256 + tid;
            int r = lin >> 3, sg = lin & 7;
            cp16(sA + r * 144 + sg * 16, Ag + (size_t)r * 1024 + sg * 16);
            cp16(sB + r * 144 + sg * 16, Bg + (size_t)r * 1024 + sg * 16);
        }
        asm volatile("cp.async.commit_group;");
    };

    cp_stage(0);

    for (int s = 0; s < NS; s++) {
        if (s + 1 < NS) {
            cp_stage(s + 1);
            asm volatile("cp.async.wait_group 1;");
        } else {
            asm volatile("cp.async.wait_group 0;");
        }
        __syncthreads();

        uint32_t sA = smem_u + (s & 1) * STAGE_BYTES;
        uint32_t sB = sA + A_BYTES;

#pragma unroll
        for (int kk = 0; kk < 4; kk++) {
            uint32_t a[4][4];
#pragma unroll
            for (int i = 0; i < 4; i++) {
                uint32_t row = wm * 64 + i * 16 + (lane & 15);
                uint32_t col = kk * 16 + ((lane >> 4) << 3);
                ldsm4(a[i], sA + (row * 72 + col) * 2);
            }
            uint32_t bf[2][4];
#pragma unroll
            for (int j2 = 0; j2 < 2; j2++) {
                uint32_t row = wn * 32 + j2 * 16 + (lane & 7) + ((lane >> 4) << 3);
                uint32_t col = kk * 16 + (((lane >> 3) & 1) << 3);
                ldsm4(bf[j2], sB + (row * 72 + col) * 2);
            }
#pragma unroll
            for (int i = 0; i < 4; i++)
#pragma unroll
                for (int jj = 0; jj < 4; jj++) {
                    uint32_t b0 = bf[jj >> 1][(jj & 1) * 2 + 0];
                    uint32_t b1 = bf[jj >> 1][(jj & 1) * 2 + 1];
                    mma16816h(acc[i][jj], a[i], b0, b1);
                }
        }
        if (MODE == 0 && s == 7) {
#pragma unroll
            for (int i = 0; i < 4; i++)
#pragma unroll
                for (int j = 0; j < 4; j++)
#pragma unroll
                    for (int e = 0; e < 4; e++) acc[i][j][e] *= 0.000244140625f;
        }
        __syncthreads();
    }

    int g = lane >> 2, tg = lane & 3;

    if (MODE == 0) {
        // ---- BN + LIF (vth=1) in registers: jj == t ----
        __half (*sm)[SM_STRIDE] = (__half(*)[SM_STRIDE])smem;
#pragma unroll
        for (int i = 0; i < 4; i++) {
#pragma unroll
            for (int eh = 0; eh < 2; eh++) {
                int rl = wm * 64 + i * 16 + g + eh * 8;
                float sc = scale[m0 + rl], bi = bias[m0 + rl];
#pragma unroll
                for (int e1 = 0; e1 < 2; e1++) {
                    int nl = wn * 8 + 2 * tg + e1;        // n_local 0..31
                    float v = 0.f;
#pragma unroll
                    for (int t = 0; t < T_; t++) {
                        float xv = acc[i][t][eh * 2 + e1] * sc + bi;
                        v = v + (xv - v) * 0.5f;
                        float ss = (v >= 1.0f) ? 1.0f : 0.0f;
                        if (ss != 0.f) v = 0.f;
                        sm[rl][t * 32 + nl] = __float2half(ss);
                    }
                }
            }
        }
        __syncthreads();

        int tt   = blockIdx.y >> 2;      // 0 q, 1 k, 2 v
        int msub = blockIdx.y & 3;       // 128-row block within tensor
        int b    = bz;
        int nb   = blockIdx.x;           // n base = nb*32

        __half* base = (tt == 0) ? qsp : (tt == 1) ? ksp : vsp;
#pragma unroll
        for (int p = 0; p < 2; p++) {
            int rid = p * 256 + tid;       // 0..511
            int t = rid >> 7, cl = rid & 127;
            const uint4* srow = (const uint4*)&sm[cl][t * 32];
            __half* dst = base + (size_t)t * SLICE
                        + ((size_t)(b * C_ + msub * 128 + cl)) * HW_ + nb * 32;
#pragma unroll
            for (int u = 0; u < 4; u++) ((uint4*)dst)[u] = srow[u];
        }
        if (tt == 2) {
            // vout fp32 [t,b,h,n,hd]
            int t = tid >> 6, rem = tid & 63;
            int hl = rem >> 5, n = rem & 31;
            int h = msub * 2 + hl;
            float* dst = vout + ((((size_t)(t * 32 + b) * NH + h) * HW_) + nb * 32 + n) * HD;
#pragma unroll
            for (int c4 = 0; c4 < 16; c4++) {
                float4 f;
                f.x = __half2float(sm[hl * 64 + c4 * 4 + 0][t * 32 + n]);
                f.y = __half2float(sm[hl * 64 + c4 * 4 + 1][t * 32 + n]);
                f.z = __half2float(sm[hl * 64 + c4 * 4 + 2][t * 32 + n]);
                f.w = __half2float(sm[hl * 64 + c4 * 4 + 3][t * 32 + n]);
                ((float4*)dst)[c4] = f;
            }
        }
    } else {
        // ---- proj epilogue ----
#pragma unroll
        for (int i = 0; i < 4; i++) {
            int mloc = m0 + wm * 64 + i * 16 + g;
#pragma unroll
            for (int half = 0; half < 2; half++) {
                int c = mloc + half * 8;
                float sc = scale[c], bi = bias[c], cb = cbias[c];
                float* dst = outp + (size_t)bz * CN + (size_t)c * HW_;
                const float* idp = identity + (size_t)bz * CN + (size_t)c * HW_;
#pragma unroll
                for (int jj = 0; jj < 4; jj++) {
                    int col = n0 + wn * 32 + jj * 8 + 2 * tg;
                    float2 id2 = *(const float2*)&idp[col];
                    float2 v2;
                    v2.x = (acc[i][jj][half * 2 + 0] + cb) * sc + bi + id2.x;
                    v2.y = (acc[i][jj][half * 2 + 1] + cb) * sc + bi + id2.y;
                    *(float2*)&dst[col] = v2;
                }
            }
        }
    }
}

// ---------------------------------------------------------------------------
// FUSED attn + x2 kernel, one CTA per (h, b), 256 threads.
// Compacted smem (55296 B -> 4 CTAs/SM):
//   attnT: [0, 18432)          (2 chunks x 9216, row stride 144B)
//   Phase A sv/sk: [18432, 55296)  (2 groups x 18432)
//   Phase B sq: [18432, 35840) ; sx: [35840, 54272)   (overlays Phase A area)
// ---------------------------------------------------------------------------
#define FA_AT    0
#define FA_WORK  18432
#define FA_SQ    18432
#define FA_SX    35840
#define FA_TOTAL 55296
#define SQN      136

__global__ void __launch_bounds__(256) attn_x2_kernel(
    const __half* __restrict__ ksp, const __half* __restrict__ vsp,
    const __half* __restrict__ qsp, __half* __restrict__ x2T)
{
    extern __shared__ __align__(128) char fsm[];
    uint32_t smem_u = smem_to_u32(fsm);
    int h = blockIdx.x, b = blockIdx.y;
    int tid = threadIdx.x;
    int wid = tid >> 5, lane = tid & 31;
    int g = lane >> 2, tg = lane & 3;

    // ---------------- Phase A: attn ----------------
    {
        int group = tid >> 7;         // == chunk
        int gtid = tid & 127;
        int gwid = gtid >> 5;
        uint32_t sv_u = smem_u + FA_WORK + group * 18432;
        uint32_t sk_u = sv_u + 9216;
        char* sv_c = fsm + FA_WORK + group * 18432;
        char* sk_c = sv_c + 9216;

        float acc[8][4];
#pragma unroll
        for (int j = 0; j < 8; j++)
#pragma unroll
            for (int e = 0; e < 4; e++) acc[j][e] = 0.f;

        for (int st = 0; st < 8; st++) {
            int t = group * 2 + (st >> 2);
            int n0 = (st & 3) * 64;
            size_t base = (size_t)t * SLICE + ((size_t)(b * C_ + h * HD)) * HW_ + n0;
#pragma unroll
            for (int l = 0; l < 4; l++) {
                int lin = l * 128 + gtid;
                int r = lin >> 3, sg = lin & 7;
                *(uint4*)(sv_c + r * 144 + sg * 16) =
                    *(const uint4*)(vsp + base + (size_t)r * HW_ + sg * 8);
                *(uint4*)(sk_c + r * 144 + sg * 16) =
                    *(const uint4*)(ksp + base + (size_t)r * HW_ + sg * 8);
            }
            __syncthreads();

#pragma unroll
            for (int kk = 0; kk < 4; kk++) {
                uint32_t a[4];
                {
                    uint32_t row = gwid * 16 + (lane & 15);
                    uint32_t col = kk * 16 + ((lane >> 4) << 3);
                    ldsm4(a, sv_u + (row * 72 + col) * 2);
                }
                uint32_t bf[4][4];
#pragma unroll
                for (int j2 = 0; j2 < 4; j2++) {
                    uint32_t row = j2 * 16 + (lane & 7) + ((lane >> 4) << 3);
                    uint32_t col = kk * 16 + (((lane >> 3) & 1) << 3);
                    ldsm4(bf[j2], sk_u + (row * 72 + col) * 2);
                }
#pragma unroll
                for (int j = 0; j < 8; j++)
                    mma16816h(acc[j], a, bf[j >> 1][(j & 1) * 2], bf[j >> 1][(j & 1) * 2 + 1]);
            }
            __syncthreads();
        }

        // store attnT (values = count/16, exact) to smem, row stride 72 halves
        char* at_c = fsm + FA_AT + group * 9216;
#pragma unroll
        for (int j = 0; j < 8; j++)
#pragma unroll
            for (int e = 0; e < 2; e++) {
                int row = gwid * 16 + g + e * 8;       // de
                int col = j * 8 + tg * 2;              // dh
                __half2 h2 = __floats2half2_rn(acc[j][e * 2] * 0.0625f,
                                               acc[j][e * 2 + 1] * 0.0625f);
                *(__half2*)(at_c + (row * 72 + col) * 2) = h2;
            }
    }
    __syncthreads();

    // ---------------- Phase B: x2 ----------------
    int wm = wid >> 1, wn = wid & 1;
    uint32_t sq_u = smem_u + FA_SQ;
    __half (*sx)[72] = (__half(*)[72])(fsm + FA_SX);

    for (int nhalf = 0; nhalf < 2; nhalf++) {
        float mem[8][4];
#pragma unroll
        for (int j = 0; j < 8; j++)
#pragma unroll
            for (int e = 0; e < 4; e++) mem[j][e] = 0.f;

#pragma unroll
        for (int t = 0; t < T_; t++) {
            uint32_t sa_u = smem_u + FA_AT + (t >> 1) * 9216;
            {
                const __half* qp = qsp + (size_t)t * SLICE
                                 + ((size_t)(b * C_ + h * HD)) * HW_ + nhalf * 128;
#pragma unroll
                for (int l = 0; l < 4; l++) {
                    int lin = l * 256 + tid;
                    int r = lin >> 4, sg = lin & 15;
                    *(uint4*)(fsm + FA_SQ + r * (SQN * 2) + sg * 16) =
                        *(const uint4*)(qp + (size_t)r * HW_ + sg * 8);
                }
            }
            __syncthreads();

            float acc[8][4];
#pragma unroll
            for (int j = 0; j < 8; j++)
#pragma unroll
                for (int e = 0; e < 4; e++) acc[j][e] = 0.f;

#pragma unroll
            for (int kk = 0; kk < 4; kk++) {
                uint32_t a[4];
                {
                    uint32_t row = wm * 16 + (lane & 15);
                    uint32_t col = kk * 16 + ((lane >> 4) << 3);
                    ldsm4(a, sa_u + (row * 72 + col) * 2);
                }
                uint32_t bf[4][4];
#pragma unroll
                for (int j2 = 0; j2 < 4; j2++) {
                    uint32_t krow = kk * 16 + (((lane >> 3) & 1) << 3) + (lane & 7);
                    uint32_t ncol = wn * 64 + j2 * 16 + ((lane >> 4) << 3);
                    ldsm4t(bf[j2], sq_u + (krow * SQN + ncol) * 2);
                }
#pragma unroll
                for (int j = 0; j < 8; j++)
                    mma16816h(acc[j], a, bf[j >> 1][(j & 1) * 2], bf[j >> 1][(j & 1) * 2 + 1]);
            }

            // LIF (vth = 0.5) -> stage spikes into sx[n][de]
#pragma unroll
            for (int j = 0; j < 8; j++)
#pragma unroll
                for (int e = 0; e < 4; e++) {
                    float xv = acc[j][e];
                    mem[j][e] = mem[j][e] + (xv - mem[j][e]) * 0.5f;
                    float s = (mem[j][e] >= 0.5f) ? 1.0f : 0.0f;
                    if (s != 0.f) mem[j][e] = 0.f;
                    int n = wn * 64 + j * 8 + tg * 2 + (e & 1);
                    int de = wm * 16 + g + ((e >> 1) << 3);
                    sx[n][de] = __float2half(s);
                }
            __syncthreads();

            // coalesced write: x2T[(t*B+b)*HW + nhalf*128 + n][h*64 .. +63]
            {
                __half* obase = x2T + ((size_t)(t * B_ + b) * HW_ + nhalf * 128) * C_ + h * HD;
#pragma unroll
                for (int l = 0; l < 2; l++) {
                    int idx = l * 256 + tid;        // 0..511
                    int n = idx >> 2, seg = idx & 3;
                    *(uint4*)(obase + (size_t)n * C_ + seg * 16) =
                        *(const uint4*)(&sx[n][seg * 16]);
                }
            }
            __syncthreads();
        }
    }
}

// ---------------------------------------------------------------------------
extern "C" void kernel_launch(void* const* d_in, const int* in_sizes, int n_in,
                              void* d_out, int out_size)
{
    const float* x       = (const float*)d_in[0];
    const float* Wq      = (const float*)d_in[1];
    const float* q_scale = (const float*)d_in[2];
    const float* q_bias  = (const float*)d_in[3];
    const float* Wk      = (const float*)d_in[4];
    const float* k_scale = (const float*)d_in[5];
    const float* k_bias  = (const float*)d_in[6];
    const float* Wv      = (const float*)d_in[7];
    const float* v_scale = (const float*)d_in[8];
    const float* v_bias  = (const float*)d_in[9];
    const float* Wp      = (const float*)d_in[10];
    const float* bp      = (const float*)d_in[11];
    const float* p_scale = (const float*)d_in[12];
    const float* p_bias  = (const float*)d_in[13];
    float* out = (float*)d_out;

    __half *xsB, *qsp, *ksp, *vsp, *x2T, *wsplit;
    float *gscale, *gbias;
    cudaGetSymbolAddress((void**)&xsB,    g_xsB);
    cudaGetSymbolAddress((void**)&qsp,    g_qs);
    cudaGetSymbolAddress((void**)&ksp,    g_ks);
    cudaGetSymbolAddress((void**)&vsp,    g_vs);
    cudaGetSymbolAddress((void**)&x2T,    g_x2T);
    cudaGetSymbolAddress((void**)&wsplit, g_wsplit);
    cudaGetSymbolAddress((void**)&gscale, g_scale);
    cudaGetSymbolAddress((void**)&gbias,  g_bias);

    const int SMEM_BYTES = 2 * STAGE_BYTES;   // 73728
    cudaFuncSetAttribute(gemm_hmma_kernel<0>, cudaFuncAttributeMaxDynamicSharedMemorySize, SMEM_BYTES);
    cudaFuncSetAttribute(gemm_hmma_kernel<1>, cudaFuncAttributeMaxDynamicSharedMemorySize, SMEM_BYTES);
    cudaFuncSetAttribute(attn_x2_kernel, cudaFuncAttributeMaxDynamicSharedMemorySize, FA_TOTAL);

    // 0+1 merged: LIF+transpose (blocks 0..1023) + weight split (1024..2047)
    prep_kernel<<<2048, 256>>>(x, xsB, Wq, Wk, Wv, Wp, wsplit,
                               q_scale, q_bias, k_scale, k_bias, v_scale, v_bias,
                               gscale, gbias);

    // 2. q/k/v conv + BN + LIF fused in GEMM epilogue -> q/k/v [t,b,c,n] + vout
    gemm_hmma_kernel<0><<<dim3(8, 12, 32), 256, SMEM_BYTES>>>(
        wsplit, xsB, qsp, ksp, vsp, out + TOTAL,
        gscale, gbias, nullptr, nullptr, nullptr, 0);

    // 3+4 fused: attn (smem) + x2 + LIF(0.5) -> x2T [tb][n][c]
    attn_x2_kernel<<<dim3(NH, B_), 256, FA_TOTAL>>>(ksp, vsp, qsp, x2T);

    // 5. proj conv (hi split) + BN + identity via HMMA -> out[0 : TOTAL)
    gemm_hmma_kernel<1><<<dim3(2, 4, 128), 256, SMEM_BYTES>>>(
        wsplit, x2T, nullptr, nullptr, nullptr, nullptr,
        p_scale, p_bias, bp, x, out, 1536);
}